// round 12
// baseline (speedup 1.0000x reference)
#include <cuda_runtime.h>
#include <cuda_bf16.h>
#include <cstdint>

// ---------------------------------------------------------------------------
// Problem constants
// ---------------------------------------------------------------------------
static constexpr int B_  = 8;
static constexpr int S_  = 1024;
static constexpr int D_  = 1024;
static constexpr int H_  = 16;
static constexpr int DK_ = 64;
static constexpr int V_  = 65;            // 2*MAXREL+1
static constexpr int BH_ = B_ * H_;       // 128
static constexpr int MROWS = B_ * S_;     // 8192
static constexpr int NROW  = BH_ * S_;    // 131072 (b,h,s) rows
static constexpr size_t SCORES_ELEMS = (size_t)BH_ * S_ * S_;  // 134217728
static constexpr int FINAL_ELEMS = MROWS * D_;                 // 8388608

// ---------------------------------------------------------------------------
// Device scratch (static — no allocation allowed)
// ---------------------------------------------------------------------------
__device__ float g_qp[BH_ * S_ * DK_];     // Q projection, [bh][s][d], pre-scaled 1/8
__device__ float g_vp[BH_ * S_ * DK_];
__device__ float g_qrel[NROW * V_];        // q . rel_k[t]
__device__ float g_w[NROW * V_];           // relative-value buckets (normalized)
__device__ float g_scores[SCORES_ELEMS];   // unnormalized p = exp(folded score)
__device__ float g_ctx[MROWS * D_];        // [b][s][h*64+d]
__device__ float g_stats[NROW];            // per-row 1/sum
__device__ unsigned g_flags;
__device__ int g_mask_mode;

// bf16 split-precision fragment images (mma.sync m16n8k16 register order)
__device__ uint32_t g_Ahi[MROWS * D_ / 2];   // 16MB
__device__ uint32_t g_Alo[MROWS * D_ / 2];   // 16MB
__device__ uint32_t g_Whi[D_ * D_ / 2];      // 2MB
__device__ uint32_t g_Wlo[D_ * D_ / 2];      // 2MB

// per-head fragment images for K (QK B-operand) and V (AV B-operand)
static constexpr int HEADW = BH_ * S_ * DK_ / 2;   // 4.19M words each
__device__ uint32_t g_Khi[HEADW];
__device__ uint32_t g_Klo[HEADW];
__device__ uint32_t g_Vhi[HEADW];
__device__ uint32_t g_Vlo[HEADW];

// ---------------------------------------------------------------------------
// bf16 split helpers
// ---------------------------------------------------------------------------
__device__ __forceinline__ void split_pair(float x0, float x1,
                                           uint32_t& h, uint32_t& l) {
    __nv_bfloat16 h0 = __float2bfloat16(x0);
    __nv_bfloat16 h1 = __float2bfloat16(x1);
    __nv_bfloat16 l0 = __float2bfloat16(x0 - __bfloat162float(h0));
    __nv_bfloat16 l1 = __float2bfloat16(x1 - __bfloat162float(h1));
    h = (uint32_t)__bfloat16_as_ushort(h0) | ((uint32_t)__bfloat16_as_ushort(h1) << 16);
    l = (uint32_t)__bfloat16_as_ushort(l0) | ((uint32_t)__bfloat16_as_ushort(l1) << 16);
}

// mma.sync m16n8k16 bf16: C += A*B (A row-major 16x16, B col-major 16x8)
__device__ __forceinline__ void mma_bf16(float* c,
                                         uint32_t a0, uint32_t a1, uint32_t a2, uint32_t a3,
                                         uint32_t b0, uint32_t b1) {
    asm volatile(
        "mma.sync.aligned.m16n8k16.row.col.f32.bf16.bf16.f32 "
        "{%0,%1,%2,%3}, {%4,%5,%6,%7}, {%8,%9}, {%0,%1,%2,%3};"
        : "+f"(c[0]), "+f"(c[1]), "+f"(c[2]), "+f"(c[3])
        : "r"(a0), "r"(a1), "r"(a2), "r"(a3), "r"(b0), "r"(b1));
}

// ---------------------------------------------------------------------------
// Mask dtype detection (bool serialization is ambiguous: f32/u8/i32/bf16)
// ---------------------------------------------------------------------------
__global__ void k_reset_flags() { g_flags = 0u; }

__global__ void k_detect_mask(const unsigned* __restrict__ w, int n) {
    unsigned f = 0;
    for (int i = blockIdx.x * blockDim.x + threadIdx.x; i < n;
         i += gridDim.x * blockDim.x) {
        unsigned x = w[i];
        if (x == 0u) continue;
        if (x == 0x3F800000u) { f |= 1u; continue; }
        if ((x & ~0x01010101u) == 0u) { f |= (x == 1u) ? 16u : 2u; continue; }
        unsigned lo = x & 0xFFFFu, hi = x >> 16;
        if ((lo == 0u || lo == 0x3F80u) && (hi == 0u || hi == 0x3F80u)) f |= 4u;
        else f |= 8u;
    }
    if (f) atomicOr(&g_flags, f);
}

__global__ void k_finalize_mask() {
    unsigned fl = g_flags;
    int m;
    if      (fl & 4u) m = 3;
    else if (fl & 1u) m = 0;
    else if (fl & 2u) m = 1;
    else              m = 2;
    g_mask_mode = m;
}

// paired mask test: elements idx, idx+1 with a single load
__device__ __forceinline__ void mask2_at(const void* m, int mode, size_t idx,
                                         bool& a, bool& b) {
    if (mode == 1) {
        unsigned short w = *(const unsigned short*)((const unsigned char*)m + idx);
        a = (w & 0xFFu) != 0; b = (w >> 8) != 0;
    } else if (mode == 0) {
        float2 v = *(const float2*)((const float*)m + idx);
        a = v.x != 0.0f; b = v.y != 0.0f;
    } else if (mode == 3) {
        unsigned w = *(const unsigned*)((const unsigned short*)m + idx);
        a = (w & 0xFFFFu) != 0; b = (w >> 16) != 0;
    } else {
        int2 v = *(const int2*)((const int*)m + idx);
        a = v.x != 0; b = v.y != 0;
    }
}

// ---------------------------------------------------------------------------
// Pack A[8192,1024] fp32 -> hi/lo fragment images (projection GEMM operand).
// ---------------------------------------------------------------------------
__global__ __launch_bounds__(256) void k_pack_a(
    const float* __restrict__ src,
    uint32_t* __restrict__ hi, uint32_t* __restrict__ lo)
{
    int idx = blockIdx.x * 256 + threadIdx.x;
    int r    = idx & 3;
    int lane = (idx >> 2) & 31;
    int ks   = (idx >> 7) & 63;
    int mblk = idx >> 13;
    int row = mblk * 16 + (lane >> 2) + (r & 1) * 8;
    int col = ks * 16 + (lane & 3) * 2 + (r >> 1) * 8;
    float2 x = *(const float2*)(src + (size_t)row * 1024 + col);
    uint32_t h, l;
    split_pair(x.x, x.y, h, l);
    hi[idx] = h; lo[idx] = l;
}

// ---------------------------------------------------------------------------
// Pack W[1024k,1024n] fp32 -> hi/lo B fragment images (col-major operand).
// ---------------------------------------------------------------------------
__global__ __launch_bounds__(256) void k_pack_w(
    const float* __restrict__ W,
    uint32_t* __restrict__ hi, uint32_t* __restrict__ lo)
{
    int idx = blockIdx.x * 256 + threadIdx.x;
    int r    = idx & 3;
    int lane = (idx >> 2) & 31;
    int ks   = (idx >> 7) & 63;
    int n16  = idx >> 13;
    int n = n16 * 16 + (r >> 1) * 8 + (lane >> 2);
    int k = ks * 16 + (lane & 3) * 2 + (r & 1) * 8;
    float x0 = W[(size_t)k * 1024 + n];
    float x1 = W[(size_t)(k + 1) * 1024 + n];
    uint32_t h, l;
    split_pair(x0, x1, h, l);
    hi[idx] = h; lo[idx] = l;
}

// V as B-operand: vp[bh][s][64], B[k=s][n=d] = vp[k][n] -> [bh][n16=4][ks64][lane][4]
__global__ __launch_bounds__(256) void k_pack_vb(
    const float* __restrict__ vp,
    uint32_t* __restrict__ hi, uint32_t* __restrict__ lo)
{
    int idx = blockIdx.x * 256 + threadIdx.x;
    int r    = idx & 3;
    int lane = (idx >> 2) & 31;
    int ks   = (idx >> 7) & 63;
    int n16  = (idx >> 13) & 3;
    int bh   = idx >> 15;
    int n = n16 * 16 + (r >> 1) * 8 + (lane >> 2);
    int k = ks * 16 + (lane & 3) * 2 + (r & 1) * 8;
    float x0 = vp[(((size_t)bh << 10) + k) * 64 + n];
    float x1 = vp[(((size_t)bh << 10) + k + 1) * 64 + n];
    uint32_t h, l;
    split_pair(x0, x1, h, l);
    hi[idx] = h; lo[idx] = l;
}

// ---------------------------------------------------------------------------
// Tensor-core split-bf16 GEMM: C[8192,1024] = A @ W (+bias, epilogue layout)
// MODE 0: head layout [b,h,s,64] with (acc+bias)*scale
// MODE 1: row-major [M,N] + bias
// MODE 2: emit K B-fragment images (khi/klo) directly, coalesced uint4 stores
// ---------------------------------------------------------------------------
template <int MODE>
__global__ __launch_bounds__(256) void k_mma_gemm(
    const uint4* __restrict__ Ahi, const uint4* __restrict__ Alo,
    const uint4* __restrict__ Bhi, const uint4* __restrict__ Blo,
    const float* __restrict__ bias, float scale, float* __restrict__ out,
    uint32_t* __restrict__ fhi, uint32_t* __restrict__ flo)
{
    const int tid = threadIdx.x, lane = tid & 31, wid = tid >> 5;
    const int warp_m = wid & 1, warp_n = wid >> 1;
    const int ntile = blockIdx.x, mtile = blockIdx.y;
    const int mb0 = mtile * 8 + warp_m * 4;
    const int nb0 = ntile * 8 + warp_n * 2;

    float acc[4][4][4];
#pragma unroll
    for (int i = 0; i < 4; i++)
#pragma unroll
        for (int j = 0; j < 4; j++)
#pragma unroll
            for (int c = 0; c < 4; c++) acc[i][j][c] = 0.f;

    uint4 ah[2][4], al[2][4], bh[2][2], bl[2][2];

#pragma unroll
    for (int i = 0; i < 4; i++) {
        ah[0][i] = Ahi[((size_t)(mb0 + i) * 64 + 0) * 32 + lane];
        al[0][i] = Alo[((size_t)(mb0 + i) * 64 + 0) * 32 + lane];
    }
#pragma unroll
    for (int j = 0; j < 2; j++) {
        bh[0][j] = Bhi[((size_t)(nb0 + j) * 64 + 0) * 32 + lane];
        bl[0][j] = Blo[((size_t)(nb0 + j) * 64 + 0) * 32 + lane];
    }

#pragma unroll 2
    for (int ks = 0; ks < 64; ks++) {
        const int cb = ks & 1, nb = cb ^ 1;
        if (ks + 1 < 64) {
#pragma unroll
            for (int i = 0; i < 4; i++) {
                ah[nb][i] = Ahi[((size_t)(mb0 + i) * 64 + ks + 1) * 32 + lane];
                al[nb][i] = Alo[((size_t)(mb0 + i) * 64 + ks + 1) * 32 + lane];
            }
#pragma unroll
            for (int j = 0; j < 2; j++) {
                bh[nb][j] = Bhi[((size_t)(nb0 + j) * 64 + ks + 1) * 32 + lane];
                bl[nb][j] = Blo[((size_t)(nb0 + j) * 64 + ks + 1) * 32 + lane];
            }
        }
#pragma unroll
        for (int i = 0; i < 4; i++) {
            const uint4 A = ah[cb][i], L = al[cb][i];
#pragma unroll
            for (int j = 0; j < 2; j++) {
                const uint4 Bh = bh[cb][j], Bl = bl[cb][j];
                mma_bf16(acc[i][j * 2], A.x, A.y, A.z, A.w, Bh.x, Bh.y);
                mma_bf16(acc[i][j * 2], L.x, L.y, L.z, L.w, Bh.x, Bh.y);
                mma_bf16(acc[i][j * 2], A.x, A.y, A.z, A.w, Bl.x, Bl.y);
                mma_bf16(acc[i][j * 2 + 1], A.x, A.y, A.z, A.w, Bh.z, Bh.w);
                mma_bf16(acc[i][j * 2 + 1], L.x, L.y, L.z, L.w, Bh.z, Bh.w);
                mma_bf16(acc[i][j * 2 + 1], A.x, A.y, A.z, A.w, Bl.z, Bl.w);
            }
        }
    }

    if (MODE == 2) {
#pragma unroll
        for (int i = 0; i < 4; i++) {
            const int row = mtile * 128 + warp_m * 64 + i * 16 + (lane >> 2);
            const int bb = row >> 10;
            const int n16 = (row >> 4) & 63;
#pragma unroll
            for (int jp = 0; jp < 2; jp++) {
                const int colb = ntile * 128 + warp_n * 32 + jp * 16 + (lane & 3) * 2;
                const int hh = colb >> 6;
                const int ks2 = (colb & 63) >> 4;
                uint32_t hw[4], lw[4];
#pragma unroll
                for (int half = 0; half < 2; half++) {
#pragma unroll
                    for (int jj = 0; jj < 2; jj++) {
                        const int j = jp * 2 + jj;
                        const int c = ntile * 128 + warp_n * 32 + j * 8 + (lane & 3) * 2;
                        float v0 = acc[i][j][half * 2 + 0] + bias[c];
                        float v1 = acc[i][j][half * 2 + 1] + bias[c + 1];
                        split_pair(v0, v1, hw[jj + half * 2], lw[jj + half * 2]);
                    }
                }
                size_t widx =
                    ((((size_t)((bb * 16 + hh) * 64 + n16)) * 4 + ks2) * 32 + lane) * 4;
                *(uint4*)&fhi[widx] = make_uint4(hw[0], hw[1], hw[2], hw[3]);
                *(uint4*)&flo[widx] = make_uint4(lw[0], lw[1], lw[2], lw[3]);
            }
        }
        return;
    }

#pragma unroll
    for (int i = 0; i < 4; i++) {
        const int row0 = mtile * 128 + warp_m * 64 + i * 16 + (lane >> 2);
#pragma unroll
        for (int j = 0; j < 4; j++) {
            const int col0 = ntile * 128 + warp_n * 32 + j * 8 + (lane & 3) * 2;
            const float b0 = bias[col0], b1 = bias[col0 + 1];
#pragma unroll
            for (int half = 0; half < 2; half++) {
                const int row = row0 + half * 8;
                float v0 = acc[i][j][half * 2 + 0] + b0;
                float v1 = acc[i][j][half * 2 + 1] + b1;
                if (MODE == 0) {
                    v0 *= scale; v1 *= scale;
                    const int bb = row >> 10, ss = row & 1023;
                    const int hh = col0 >> 6, dk = col0 & 63;
                    float* dst = out + ((((size_t)(bb * 16 + hh)) << 10) + ss) * 64 + dk;
                    *(float2*)dst = make_float2(v0, v1);
                } else {
                    *(float2*)(out + (size_t)row * 1024 + col0) = make_float2(v0, v1);
                }
            }
        }
    }
}

// ---------------------------------------------------------------------------
// qrel[bhs][t] = sum_d qp[bhs][d] * rel_k[t][d]   (q already scaled)
// ---------------------------------------------------------------------------
__global__ __launch_bounds__(256) void k_qrel(const float* __restrict__ qp,
                                              const float* __restrict__ rel_k,
                                              float* __restrict__ qrel)
{
    __shared__ float rk[V_ * 65];
    __shared__ float qs[8 * DK_];
    const int tid = threadIdx.x;
    const long long r0 = (long long)blockIdx.x * 8;
    for (int i = tid; i < V_ * DK_; i += 256) {
        int t = i / DK_, d = i % DK_;
        rk[t * 65 + d] = rel_k[i];
    }
    for (int i = tid; i < 8 * DK_; i += 256) qs[i] = qp[r0 * DK_ + i];
    __syncthreads();
    const int wr = tid >> 5, lane = tid & 31;
    for (int t = lane; t < V_; t += 32) {
        float s = 0.f;
#pragma unroll
        for (int d = 0; d < DK_; d++) s += qs[wr * DK_ + d] * rk[t * 65 + d];
        qrel[(r0 + wr) * V_ + t] = s;
    }
}

// fold helper: -log(adj) with adj in {1,2} fast paths
__device__ __forceinline__ float adj_fold(float av) {
    if (av == 1.0f) return 0.f;
    if (av == 2.0f) return 0.69314718055994530942f;
    return __logf(av);
}

// ---------------------------------------------------------------------------
// Fused attention: QK mma + fold + p=exp(s) (no max subtraction — scores are
// bounded) + p store + row sum + AV mma + rel-value buckets, normalized at end.
// grid (8 qtiles, 128 bh), 256 thr; warp = 16 q rows x all 1024 k.
// ---------------------------------------------------------------------------
__global__ __launch_bounds__(256) void k_qk_av(
    const float* __restrict__ qp,
    const uint4* __restrict__ Khi, const uint4* __restrict__ Klo,
    const uint4* __restrict__ Vhi, const uint4* __restrict__ Vlo,
    const float* __restrict__ qrel, const void* __restrict__ mask,
    const float* __restrict__ adj, float* __restrict__ pu,
    float* __restrict__ stats, float* __restrict__ wbuf,
    float* __restrict__ ctx)
{
    __shared__ float sinv[8][16];
    const int tid = threadIdx.x, lane = tid & 31, wid = tid >> 5;
    const int qtile = blockIdx.x, bh = blockIdx.y;
    const int row0 = qtile * 128 + wid * 16 + (lane >> 2);
    const int row1 = row0 + 8;
    const size_t qbase = ((size_t)bh << 10);

    // Q fragments directly from qp (split on the fly, reused for all k)
    uint32_t qh[4][4], ql[4][4];
#pragma unroll
    for (int ks = 0; ks < 4; ks++) {
        const int c0 = ks * 16 + (lane & 3) * 2;
        float2 x0 = *(const float2*)(qp + (qbase + row0) * 64 + c0);
        float2 x1 = *(const float2*)(qp + (qbase + row1) * 64 + c0);
        float2 x2 = *(const float2*)(qp + (qbase + row0) * 64 + c0 + 8);
        float2 x3 = *(const float2*)(qp + (qbase + row1) * 64 + c0 + 8);
        split_pair(x0.x, x0.y, qh[ks][0], ql[ks][0]);
        split_pair(x1.x, x1.y, qh[ks][1], ql[ks][1]);
        split_pair(x2.x, x2.y, qh[ks][2], ql[ks][2]);
        split_pair(x3.x, x3.y, qh[ks][3], ql[ks][3]);
    }

    const int mode = g_mask_mode;
    const int bb = bh >> 4;
    const float* qr0 = qrel + (qbase + row0) * V_;
    const float* qr1 = qrel + (qbase + row1) * V_;
    const float qlo0 = qr0[0], qhi0 = qr0[64];
    const float qlo1 = qr1[0], qhi1 = qr1[64];
    const size_t arow0 = (qbase + row0) << 10;
    const size_t arow1 = (qbase + row1) << 10;
    const size_t mrow0 = (((size_t)bb << 10) + row0) << 10;
    const size_t mrow1 = (((size_t)bb << 10) + row1) << 10;
    const size_t kb = (size_t)bh * 8192;   // uint4 per head K/V image

    // zero this warp's 16 wbuf rows
    const size_t wrbase = qbase + qtile * 128 + wid * 16;
    for (int i = lane; i < 16 * V_; i += 32) wbuf[wrbase * V_ + i] = 0.f;
    __syncwarp();
    float* wr0 = wbuf + (qbase + row0) * V_;
    float* wr1 = wr0 + (size_t)8 * V_;

    float s0 = 0.f, s1 = 0.f;
    float pre0 = 0.f, suf0 = 0.f, pre1 = 0.f, suf1 = 0.f;
    float cacc[4][2][4];
#pragma unroll
    for (int nb = 0; nb < 4; nb++)
#pragma unroll
        for (int e = 0; e < 2; e++)
#pragma unroll
            for (int c = 0; c < 4; c++) cacc[nb][e][c] = 0.f;

#pragma unroll 1
    for (int kt = 0; kt < 16; kt++) {      // 64-col tiles
        float acc[8][4];
#pragma unroll
        for (int p = 0; p < 8; p++)
#pragma unroll
            for (int c = 0; c < 4; c++) acc[p][c] = 0.f;

#pragma unroll
        for (int ks = 0; ks < 4; ks++) {
#pragma unroll
            for (int b = 0; b < 4; b++) {
                const int n16 = kt * 4 + b;
                const uint4 Bh = Khi[kb + (size_t)(n16 * 4 + ks) * 32 + lane];
                const uint4 Bl = Klo[kb + (size_t)(n16 * 4 + ks) * 32 + lane];
                mma_bf16(acc[b*2],   qh[ks][0], qh[ks][1], qh[ks][2], qh[ks][3], Bh.x, Bh.y);
                mma_bf16(acc[b*2],   ql[ks][0], ql[ks][1], ql[ks][2], ql[ks][3], Bh.x, Bh.y);
                mma_bf16(acc[b*2],   qh[ks][0], qh[ks][1], qh[ks][2], qh[ks][3], Bl.x, Bl.y);
                mma_bf16(acc[b*2+1], qh[ks][0], qh[ks][1], qh[ks][2], qh[ks][3], Bh.z, Bh.w);
                mma_bf16(acc[b*2+1], ql[ks][0], ql[ks][1], ql[ks][2], ql[ks][3], Bh.z, Bh.w);
                mma_bf16(acc[b*2+1], qh[ks][0], qh[ks][1], qh[ks][2], qh[ks][3], Bl.z, Bl.w);
            }
        }

        // tile-level relative-position classification (band is |k-q|<32)
        const int tlo = kt * 64;
        const bool pre0a = (tlo + 63 <= row0 - 32);
        const bool suf0a = (tlo >= row0 + 32);
        const bool pre1a = (tlo + 63 <= row1 - 32);
        const bool suf1a = (tlo >= row1 + 32);

        // fold + exp + store p + sum
#pragma unroll
        for (int p = 0; p < 8; p++) {
            const int col = tlo + p * 8 + (lane & 3) * 2;
            // row0 pair
            {
                float r0x, r0y;
                if (pre0a)      { r0x = qlo0; r0y = qlo0; }
                else if (suf0a) { r0x = qhi0; r0y = qhi0; }
                else {
                    int d0 = col - row0;     d0 = d0 < -32 ? -32 : (d0 > 32 ? 32 : d0);
                    int d1 = col + 1 - row0; d1 = d1 < -32 ? -32 : (d1 > 32 ? 32 : d1);
                    r0x = qr0[d0 + 32]; r0y = qr0[d1 + 32];
                }
                float v0 = acc[p][0] + r0x;
                float v1 = acc[p][1] + r0y;
                float2 av = *(const float2*)(adj + arow0 + col);
                bool ma, mb;
                mask2_at(mask, mode, mrow0 + col, ma, mb);
                if (ma || av.x == 0.0f) v0 = -1e30f; else v0 -= adj_fold(av.x);
                if (mb || av.y == 0.0f) v1 = -1e30f; else v1 -= adj_fold(av.y);
                float p0 = __expf(v0), p1 = __expf(v1);
                *(float2*)(pu + arow0 + col) = make_float2(p0, p1);
                s0 += p0 + p1;
                acc[p][0] = p0; acc[p][1] = p1;
            }
            // row1 pair
            {
                float r1x, r1y;
                if (pre1a)      { r1x = qlo1; r1y = qlo1; }
                else if (suf1a) { r1x = qhi1; r1y = qhi1; }
                else {
                    int d0 = col - row1;     d0 = d0 < -32 ? -32 : (d0 > 32 ? 32 : d0);
                    int d1 = col + 1 - row1; d1 = d1 < -32 ? -32 : (d1 > 32 ? 32 : d1);
                    r1x = qr1[d0 + 32]; r1y = qr1[d1 + 32];
                }
                float v0 = acc[p][2] + r1x;
                float v1 = acc[p][3] + r1y;
                float2 av = *(const float2*)(adj + arow1 + col);
                bool ma, mb;
                mask2_at(mask, mode, mrow1 + col, ma, mb);
                if (ma || av.x == 0.0f) v0 = -1e30f; else v0 -= adj_fold(av.x);
                if (mb || av.y == 0.0f) v1 = -1e30f; else v1 -= adj_fold(av.y);
                float p0 = __expf(v0), p1 = __expf(v1);
                *(float2*)(pu + arow1 + col) = make_float2(p0, p1);
                s1 += p0 + p1;
                acc[p][2] = p0; acc[p][3] = p1;
            }
        }

        // rel-value buckets (unnormalized), tile-classified on the 64-col tile
        if (pre0a) {
#pragma unroll
            for (int p = 0; p < 8; p++) pre0 += acc[p][0] + acc[p][1];
        } else if (suf0a) {
#pragma unroll
            for (int p = 0; p < 8; p++) suf0 += acc[p][0] + acc[p][1];
        } else {
#pragma unroll
            for (int p = 0; p < 8; p++) {
                const int col = tlo + p * 8 + (lane & 3) * 2;
#pragma unroll
                for (int e = 0; e < 2; e++) {
                    int d = col + e - row0;
                    float v = acc[p][e];
                    if (d <= -32)      pre0 += v;
                    else if (d >= 32)  suf0 += v;
                    else               wr0[d + 32] = v;
                }
            }
        }
        if (pre1a) {
#pragma unroll
            for (int p = 0; p < 8; p++) pre1 += acc[p][2] + acc[p][3];
        } else if (suf1a) {
#pragma unroll
            for (int p = 0; p < 8; p++) suf1 += acc[p][2] + acc[p][3];
        } else {
#pragma unroll
            for (int p = 0; p < 8; p++) {
                const int col = tlo + p * 8 + (lane & 3) * 2;
#pragma unroll
                for (int e = 0; e < 2; e++) {
                    int d = col + e - row1;
                    float v = acc[p][e + 2];
                    if (d <= -32)      pre1 += v;
                    else if (d >= 32)  suf1 += v;
                    else               wr1[d + 32] = v;
                }
            }
        }

        // AV mma: acc fragments ARE the A-operand fragments
#pragma unroll
        for (int j = 0; j < 4; j++) {
            uint32_t ah0, ah1, ah2, ah3, al0, al1, al2, al3;
            split_pair(acc[2*j][0],   acc[2*j][1],   ah0, al0);
            split_pair(acc[2*j][2],   acc[2*j][3],   ah1, al1);
            split_pair(acc[2*j+1][0], acc[2*j+1][1], ah2, al2);
            split_pair(acc[2*j+1][2], acc[2*j+1][3], ah3, al3);
            const int kstep = kt * 4 + j;
#pragma unroll
            for (int nb = 0; nb < 4; nb++) {
                const uint4 Bh = Vhi[kb + (size_t)(nb * 64 + kstep) * 32 + lane];
                const uint4 Bl = Vlo[kb + (size_t)(nb * 64 + kstep) * 32 + lane];
                mma_bf16(cacc[nb][0], ah0, ah1, ah2, ah3, Bh.x, Bh.y);
                mma_bf16(cacc[nb][0], al0, al1, al2, al3, Bh.x, Bh.y);
                mma_bf16(cacc[nb][0], ah0, ah1, ah2, ah3, Bl.x, Bl.y);
                mma_bf16(cacc[nb][1], ah0, ah1, ah2, ah3, Bh.z, Bh.w);
                mma_bf16(cacc[nb][1], al0, al1, al2, al3, Bh.z, Bh.w);
                mma_bf16(cacc[nb][1], ah0, ah1, ah2, ah3, Bl.z, Bl.w);
            }
        }
    }

    // reduce row sums across the 4 lanes sharing each row
#pragma unroll
    for (int o = 1; o <= 2; o <<= 1) {
        s0 += __shfl_xor_sync(0xffffffffu, s0, o);
        s1 += __shfl_xor_sync(0xffffffffu, s1, o);
        pre0 += __shfl_xor_sync(0xffffffffu, pre0, o);
        suf0 += __shfl_xor_sync(0xffffffffu, suf0, o);
        pre1 += __shfl_xor_sync(0xffffffffu, pre1, o);
        suf1 += __shfl_xor_sync(0xffffffffu, suf1, o);
    }
    const float inv0 = s0 > 0.f ? 1.f / s0 : 0.f;
    const float inv1 = s1 > 0.f ? 1.f / s1 : 0.f;

    if ((lane & 3) == 0) {
        stats[qbase + row0] = inv0;
        stats[qbase + row0 + 8] = inv1;
        sinv[wid][lane >> 2] = inv0;
        sinv[wid][(lane >> 2) + 8] = inv1;
    }
    __syncwarp();

    // normalize interior bucket entries (indices 0/64 still zero)
    for (int i = lane; i < 16 * V_; i += 32)
        wbuf[wrbase * V_ + i] *= sinv[wid][i / V_];
    __syncwarp();
    if ((lane & 3) == 0) {
        wr0[0] = pre0 * inv0; wr0[64] = suf0 * inv0;
        wr1[0] = pre1 * inv1; wr1[64] = suf1 * inv1;
    }

    // ctx write [b][s][h*64+d], normalized
    const int hh = bh & 15;
#pragma unroll
    for (int nb = 0; nb < 4; nb++)
#pragma unroll
        for (int e = 0; e < 2; e++) {
            const int d = nb * 16 + e * 8 + (lane & 3) * 2;
            float2 va = make_float2(cacc[nb][e][0] * inv0, cacc[nb][e][1] * inv0);
            float2 vb = make_float2(cacc[nb][e][2] * inv1, cacc[nb][e][3] * inv1);
            *(float2*)(ctx + (((size_t)bb << 10) + row0) * 1024 + hh * 64 + d) = va;
            *(float2*)(ctx + (((size_t)bb << 10) + row1) * 1024 + hh * 64 + d) = vb;
        }
}

// ---------------------------------------------------------------------------
// attn[i] = pu[i] * inv[row] -> d_out. Pure stream; warp per row.
// ---------------------------------------------------------------------------
__global__ __launch_bounds__(256) void k_norm_attn(
    const float* __restrict__ pu, const float* __restrict__ stats,
    float* __restrict__ attn)
{
    const int wid = threadIdx.x >> 5, lane = threadIdx.x & 31;
    const size_t row = (size_t)blockIdx.x * 8 + wid;
    const float inv = stats[row];
    const float4* src = (const float4*)(pu + (row << 10));
    float4* dst = (float4*)(attn + (row << 10));
#pragma unroll 8
    for (int i = lane; i < 256; i += 32) {
        float4 v = src[i];
        v.x *= inv; v.y *= inv; v.z *= inv; v.w *= inv;
        dst[i] = v;
    }
}

// ---------------------------------------------------------------------------
// ctx += w @ rel_v   (65x64 per row)
// ---------------------------------------------------------------------------
__global__ __launch_bounds__(256) void k_relctx(const float* __restrict__ wbuf,
                                                const float* __restrict__ rel_v,
                                                float* __restrict__ ctx)
{
    __shared__ float rv[V_ * 64];
    __shared__ float ws[4][V_];
    const int tid = threadIdx.x;
    const long long r0 = (long long)blockIdx.x * 4;
    for (int i = tid; i < V_ * 64; i += 256) rv[i] = rel_v[i];
    for (int i = tid; i < 4 * V_; i += 256)
        ws[i / V_][i % V_] = wbuf[(r0 + i / V_) * V_ + i % V_];
    __syncthreads();
    const int rr = tid >> 6;
    const int d = tid & 63;
    float acc = 0.f;
#pragma unroll
    for (int t = 0; t < V_; t++) acc += ws[rr][t] * rv[t * 64 + d];
    long long r = r0 + rr;
    int bh = (int)(r >> 10), s = (int)(r & 1023);
    int bb = bh >> 4, hh = bh & 15;
    ctx[((size_t)(bb * S_ + s)) * D_ + hh * 64 + d] += acc;
}

// ---------------------------------------------------------------------------
// Launch
// ---------------------------------------------------------------------------
extern "C" void kernel_launch(void* const* d_in, const int* in_sizes, int n_in,
                              void* d_out, int out_size)
{
    const float* key   = (const float*)d_in[0];
    const float* value = (const float*)d_in[1];
    const float* query = (const float*)d_in[2];
    const void*  mask  = d_in[3];
    const float* adj   = (const float*)d_in[4];
    const float* Wq = (const float*)d_in[5];
    const float* bq = (const float*)d_in[6];
    const float* Wk = (const float*)d_in[7];
    const float* bk = (const float*)d_in[8];
    const float* Wv = (const float*)d_in[9];
    const float* bv = (const float*)d_in[10];
    const float* Wo = (const float*)d_in[11];
    const float* bo = (const float*)d_in[12];
    const float* rel_k = (const float*)d_in[13];
    const float* rel_v = (const float*)d_in[14];
    float* outF = (float*)d_out;

    float *qp, *vp, *qrel, *wb, *sc, *ctx, *stats;
    uint32_t *ahi, *alo, *whi, *wlo, *khi, *klo, *vhi, *vlo;
    cudaGetSymbolAddress((void**)&qp,    g_qp);
    cudaGetSymbolAddress((void**)&vp,    g_vp);
    cudaGetSymbolAddress((void**)&qrel,  g_qrel);
    cudaGetSymbolAddress((void**)&wb,    g_w);
    cudaGetSymbolAddress((void**)&sc,    g_scores);
    cudaGetSymbolAddress((void**)&ctx,   g_ctx);
    cudaGetSymbolAddress((void**)&stats, g_stats);
    cudaGetSymbolAddress((void**)&ahi,   g_Ahi);
    cudaGetSymbolAddress((void**)&alo,   g_Alo);
    cudaGetSymbolAddress((void**)&whi,   g_Whi);
    cudaGetSymbolAddress((void**)&wlo,   g_Wlo);
    cudaGetSymbolAddress((void**)&khi,   g_Khi);
    cudaGetSymbolAddress((void**)&klo,   g_Klo);
    cudaGetSymbolAddress((void**)&vhi,   g_Vhi);
    cudaGetSymbolAddress((void**)&vlo,   g_Vlo);

    // mask dtype detection
    k_reset_flags<<<1, 1>>>();
    k_detect_mask<<<256, 256>>>((const unsigned*)mask, in_sizes[3] / 4);
    k_finalize_mask<<<1, 1>>>();

    const int APACK_BLOCKS = MROWS * D_ / 2 / 256;   // 16384
    const int WPACK_BLOCKS = D_ * D_ / 2 / 256;      // 2048
    const int HPACK_BLOCKS = HEADW / 256;            // 16384
    dim3 gg(8, 64);   // (ntiles, mtiles)

    // Q projection (pre-scaled by 1/8 incl. bias)
    k_pack_w<<<WPACK_BLOCKS, 256>>>(Wq, whi, wlo);
    k_pack_a<<<APACK_BLOCKS, 256>>>(query, ahi, alo);
    k_mma_gemm<0><<<gg, 256>>>((const uint4*)ahi, (const uint4*)alo,
                               (const uint4*)whi, (const uint4*)wlo, bq, 0.125f, qp,
                               nullptr, nullptr);

    // K projection — emits K B-fragment images directly
    k_pack_w<<<WPACK_BLOCKS, 256>>>(Wk, whi, wlo);
    k_pack_a<<<APACK_BLOCKS, 256>>>(key, ahi, alo);
    k_mma_gemm<2><<<gg, 256>>>((const uint4*)ahi, (const uint4*)alo,
                               (const uint4*)whi, (const uint4*)wlo, bk, 1.0f, nullptr,
                               khi, klo);

    // V projection
    k_pack_w<<<WPACK_BLOCKS, 256>>>(Wv, whi, wlo);
    k_pack_a<<<APACK_BLOCKS, 256>>>(value, ahi, alo);
    k_mma_gemm<0><<<gg, 256>>>((const uint4*)ahi, (const uint4*)alo,
                               (const uint4*)whi, (const uint4*)wlo, bv, 1.0f, vp,
                               nullptr, nullptr);

    // V B-fragment pack
    k_pack_vb<<<HPACK_BLOCKS, 256>>>(vp, vhi, vlo);

    // relative-key projection (rank-65 trick)
    k_qrel<<<NROW / 8, 256>>>(qp, rel_k, qrel);

    // fused attention: scores+softmax-sum+AV+buckets in one pass
    dim3 ag(8, BH_);
    k_qk_av<<<ag, 256>>>(qp, (const uint4*)khi, (const uint4*)klo,
                         (const uint4*)vhi, (const uint4*)vlo,
                         qrel, mask, adj, sc, stats, wb, ctx);

    // attn output stream (if the harness expects it)
    bool hasAttn = (size_t)out_size >= (size_t)FINAL_ELEMS + SCORES_ELEMS;
    if (hasAttn)
        k_norm_attn<<<NROW / 8, 256>>>(sc, stats, outF + FINAL_ELEMS);

    k_relctx<<<NROW / 4, 256>>>(wb, rel_v, ctx);

    // output projection (row-major epilogue)
    k_pack_w<<<WPACK_BLOCKS, 256>>>(Wo, whi, wlo);
    k_pack_a<<<APACK_BLOCKS, 256>>>(ctx, ahi, alo);
    k_mma_gemm<1><<<gg, 256>>>((const uint4*)ahi, (const uint4*)alo,
                               (const uint4*)whi, (const uint4*)wlo, bo, 1.0f, outF,
                               nullptr, nullptr);
}

// round 13
// speedup vs baseline: 1.2371x; 1.2371x over previous
#include <cuda_runtime.h>
#include <cuda_bf16.h>
#include <cstdint>

// ---------------------------------------------------------------------------
// Problem constants
// ---------------------------------------------------------------------------
static constexpr int B_  = 8;
static constexpr int S_  = 1024;
static constexpr int D_  = 1024;
static constexpr int H_  = 16;
static constexpr int DK_ = 64;
static constexpr int V_  = 65;            // 2*MAXREL+1
static constexpr int BH_ = B_ * H_;       // 128
static constexpr int MROWS = B_ * S_;     // 8192
static constexpr int NROW  = BH_ * S_;    // 131072 (b,h,s) rows
static constexpr size_t SCORES_ELEMS = (size_t)BH_ * S_ * S_;  // 134217728
static constexpr int FINAL_ELEMS = MROWS * D_;                 // 8388608

// ---------------------------------------------------------------------------
// Device scratch (static — no allocation allowed)
// ---------------------------------------------------------------------------
__device__ float g_qp[BH_ * S_ * DK_];     // Q projection, [bh][s][d], pre-scaled 1/8
__device__ float g_vp[BH_ * S_ * DK_];
__device__ float g_qrel[NROW * V_];        // q . rel_k[t]
__device__ float g_w[NROW * V_];           // relative-value buckets
__device__ float g_scores[SCORES_ELEMS];   // unnormalized p = exp(folded score)
__device__ float g_ctx[MROWS * D_];        // [b][s][h*64+d]
__device__ float g_stats[NROW];            // per-row 1/sum
__device__ unsigned g_flags;
__device__ int g_mask_mode;

// bf16 split-precision fragment images (mma.sync m16n8k16 register order)
__device__ uint32_t g_Ahi[MROWS * D_ / 2];   // 16MB
__device__ uint32_t g_Alo[MROWS * D_ / 2];   // 16MB
__device__ uint32_t g_Whi[D_ * D_ / 2];      // 2MB
__device__ uint32_t g_Wlo[D_ * D_ / 2];      // 2MB

// per-head fragment images for K (QK B-operand) and V (AV B-operand)
static constexpr int HEADW = BH_ * S_ * DK_ / 2;   // 4.19M words each
__device__ uint32_t g_Khi[HEADW];
__device__ uint32_t g_Klo[HEADW];
__device__ uint32_t g_Vhi[HEADW];
__device__ uint32_t g_Vlo[HEADW];

// ---------------------------------------------------------------------------
// bf16 split helpers
// ---------------------------------------------------------------------------
__device__ __forceinline__ void split_pair(float x0, float x1,
                                           uint32_t& h, uint32_t& l) {
    __nv_bfloat16 h0 = __float2bfloat16(x0);
    __nv_bfloat16 h1 = __float2bfloat16(x1);
    __nv_bfloat16 l0 = __float2bfloat16(x0 - __bfloat162float(h0));
    __nv_bfloat16 l1 = __float2bfloat16(x1 - __bfloat162float(h1));
    h = (uint32_t)__bfloat16_as_ushort(h0) | ((uint32_t)__bfloat16_as_ushort(h1) << 16);
    l = (uint32_t)__bfloat16_as_ushort(l0) | ((uint32_t)__bfloat16_as_ushort(l1) << 16);
}

// mma.sync m16n8k16 bf16: C += A*B (A row-major 16x16, B col-major 16x8)
__device__ __forceinline__ void mma_bf16(float* c,
                                         uint32_t a0, uint32_t a1, uint32_t a2, uint32_t a3,
                                         uint32_t b0, uint32_t b1) {
    asm volatile(
        "mma.sync.aligned.m16n8k16.row.col.f32.bf16.bf16.f32 "
        "{%0,%1,%2,%3}, {%4,%5,%6,%7}, {%8,%9}, {%0,%1,%2,%3};"
        : "+f"(c[0]), "+f"(c[1]), "+f"(c[2]), "+f"(c[3])
        : "r"(a0), "r"(a1), "r"(a2), "r"(a3), "r"(b0), "r"(b1));
}

// ---------------------------------------------------------------------------
// Mask dtype detection (bool serialization is ambiguous: f32/u8/i32/bf16)
// ---------------------------------------------------------------------------
__global__ void k_reset_flags() { g_flags = 0u; }

__global__ void k_detect_mask(const unsigned* __restrict__ w, int n) {
    unsigned f = 0;
    for (int i = blockIdx.x * blockDim.x + threadIdx.x; i < n;
         i += gridDim.x * blockDim.x) {
        unsigned x = w[i];
        if (x == 0u) continue;
        if (x == 0x3F800000u) { f |= 1u; continue; }
        if ((x & ~0x01010101u) == 0u) { f |= (x == 1u) ? 16u : 2u; continue; }
        unsigned lo = x & 0xFFFFu, hi = x >> 16;
        if ((lo == 0u || lo == 0x3F80u) && (hi == 0u || hi == 0x3F80u)) f |= 4u;
        else f |= 8u;
    }
    if (f) atomicOr(&g_flags, f);
}

__global__ void k_finalize_mask() {
    unsigned fl = g_flags;
    int m;
    if      (fl & 4u) m = 3;
    else if (fl & 1u) m = 0;
    else if (fl & 2u) m = 1;
    else              m = 2;
    g_mask_mode = m;
}

// paired mask test: elements idx, idx+1 with a single load
__device__ __forceinline__ void mask2_at(const void* m, int mode, size_t idx,
                                         bool& a, bool& b) {
    if (mode == 1) {
        unsigned short w = *(const unsigned short*)((const unsigned char*)m + idx);
        a = (w & 0xFFu) != 0; b = (w >> 8) != 0;
    } else if (mode == 0) {
        float2 v = *(const float2*)((const float*)m + idx);
        a = v.x != 0.0f; b = v.y != 0.0f;
    } else if (mode == 3) {
        unsigned w = *(const unsigned*)((const unsigned short*)m + idx);
        a = (w & 0xFFFFu) != 0; b = (w >> 16) != 0;
    } else {
        int2 v = *(const int2*)((const int*)m + idx);
        a = v.x != 0; b = v.y != 0;
    }
}

// ---------------------------------------------------------------------------
// Pack A[8192,1024] fp32 -> hi/lo fragment images (projection GEMM operand).
// ---------------------------------------------------------------------------
__global__ __launch_bounds__(256) void k_pack_a(
    const float* __restrict__ src,
    uint32_t* __restrict__ hi, uint32_t* __restrict__ lo)
{
    int idx = blockIdx.x * 256 + threadIdx.x;
    int r    = idx & 3;
    int lane = (idx >> 2) & 31;
    int ks   = (idx >> 7) & 63;
    int mblk = idx >> 13;
    int row = mblk * 16 + (lane >> 2) + (r & 1) * 8;
    int col = ks * 16 + (lane & 3) * 2 + (r >> 1) * 8;
    float2 x = *(const float2*)(src + (size_t)row * 1024 + col);
    uint32_t h, l;
    split_pair(x.x, x.y, h, l);
    hi[idx] = h; lo[idx] = l;
}

// ---------------------------------------------------------------------------
// Pack W[1024k,1024n] fp32 -> hi/lo B fragment images (col-major operand).
// ---------------------------------------------------------------------------
__global__ __launch_bounds__(256) void k_pack_w(
    const float* __restrict__ W,
    uint32_t* __restrict__ hi, uint32_t* __restrict__ lo)
{
    int idx = blockIdx.x * 256 + threadIdx.x;
    int r    = idx & 3;
    int lane = (idx >> 2) & 31;
    int ks   = (idx >> 7) & 63;
    int n16  = idx >> 13;
    int n = n16 * 16 + (r >> 1) * 8 + (lane >> 2);
    int k = ks * 16 + (lane & 3) * 2 + (r & 1) * 8;
    float x0 = W[(size_t)k * 1024 + n];
    float x1 = W[(size_t)(k + 1) * 1024 + n];
    uint32_t h, l;
    split_pair(x0, x1, h, l);
    hi[idx] = h; lo[idx] = l;
}

// V as B-operand: vp[bh][s][64], B[k=s][n=d] = vp[k][n] -> [bh][n16=4][ks64][lane][4]
__global__ __launch_bounds__(256) void k_pack_vb(
    const float* __restrict__ vp,
    uint32_t* __restrict__ hi, uint32_t* __restrict__ lo)
{
    int idx = blockIdx.x * 256 + threadIdx.x;
    int r    = idx & 3;
    int lane = (idx >> 2) & 31;
    int ks   = (idx >> 7) & 63;
    int n16  = (idx >> 13) & 3;
    int bh   = idx >> 15;
    int n = n16 * 16 + (r >> 1) * 8 + (lane >> 2);
    int k = ks * 16 + (lane & 3) * 2 + (r & 1) * 8;
    float x0 = vp[(((size_t)bh << 10) + k) * 64 + n];
    float x1 = vp[(((size_t)bh << 10) + k + 1) * 64 + n];
    uint32_t h, l;
    split_pair(x0, x1, h, l);
    hi[idx] = h; lo[idx] = l;
}

// ---------------------------------------------------------------------------
// Tensor-core split-bf16 GEMM: C[8192,1024] = A @ W (+bias, epilogue layout)
// MODE 0: head layout [b,h,s,64] with (acc+bias)*scale
// MODE 1: row-major [M,N] + bias
// MODE 2: emit K B-fragment images (khi/klo) directly, coalesced uint4 stores
// ---------------------------------------------------------------------------
template <int MODE>
__global__ __launch_bounds__(256) void k_mma_gemm(
    const uint4* __restrict__ Ahi, const uint4* __restrict__ Alo,
    const uint4* __restrict__ Bhi, const uint4* __restrict__ Blo,
    const float* __restrict__ bias, float scale, float* __restrict__ out,
    uint32_t* __restrict__ fhi, uint32_t* __restrict__ flo)
{
    const int tid = threadIdx.x, lane = tid & 31, wid = tid >> 5;
    const int warp_m = wid & 1, warp_n = wid >> 1;
    const int ntile = blockIdx.x, mtile = blockIdx.y;
    const int mb0 = mtile * 8 + warp_m * 4;
    const int nb0 = ntile * 8 + warp_n * 2;

    float acc[4][4][4];
#pragma unroll
    for (int i = 0; i < 4; i++)
#pragma unroll
        for (int j = 0; j < 4; j++)
#pragma unroll
            for (int c = 0; c < 4; c++) acc[i][j][c] = 0.f;

    uint4 ah[2][4], al[2][4], bh[2][2], bl[2][2];

#pragma unroll
    for (int i = 0; i < 4; i++) {
        ah[0][i] = Ahi[((size_t)(mb0 + i) * 64 + 0) * 32 + lane];
        al[0][i] = Alo[((size_t)(mb0 + i) * 64 + 0) * 32 + lane];
    }
#pragma unroll
    for (int j = 0; j < 2; j++) {
        bh[0][j] = Bhi[((size_t)(nb0 + j) * 64 + 0) * 32 + lane];
        bl[0][j] = Blo[((size_t)(nb0 + j) * 64 + 0) * 32 + lane];
    }

#pragma unroll 2
    for (int ks = 0; ks < 64; ks++) {
        const int cb = ks & 1, nb = cb ^ 1;
        if (ks + 1 < 64) {
#pragma unroll
            for (int i = 0; i < 4; i++) {
                ah[nb][i] = Ahi[((size_t)(mb0 + i) * 64 + ks + 1) * 32 + lane];
                al[nb][i] = Alo[((size_t)(mb0 + i) * 64 + ks + 1) * 32 + lane];
            }
#pragma unroll
            for (int j = 0; j < 2; j++) {
                bh[nb][j] = Bhi[((size_t)(nb0 + j) * 64 + ks + 1) * 32 + lane];
                bl[nb][j] = Blo[((size_t)(nb0 + j) * 64 + ks + 1) * 32 + lane];
            }
        }
#pragma unroll
        for (int i = 0; i < 4; i++) {
            const uint4 A = ah[cb][i], L = al[cb][i];
#pragma unroll
            for (int j = 0; j < 2; j++) {
                const uint4 Bh = bh[cb][j], Bl = bl[cb][j];
                mma_bf16(acc[i][j * 2], A.x, A.y, A.z, A.w, Bh.x, Bh.y);
                mma_bf16(acc[i][j * 2], L.x, L.y, L.z, L.w, Bh.x, Bh.y);
                mma_bf16(acc[i][j * 2], A.x, A.y, A.z, A.w, Bl.x, Bl.y);
                mma_bf16(acc[i][j * 2 + 1], A.x, A.y, A.z, A.w, Bh.z, Bh.w);
                mma_bf16(acc[i][j * 2 + 1], L.x, L.y, L.z, L.w, Bh.z, Bh.w);
                mma_bf16(acc[i][j * 2 + 1], A.x, A.y, A.z, A.w, Bl.z, Bl.w);
            }
        }
    }

    if (MODE == 2) {
#pragma unroll
        for (int i = 0; i < 4; i++) {
            const int row = mtile * 128 + warp_m * 64 + i * 16 + (lane >> 2);
            const int bb = row >> 10;
            const int n16 = (row >> 4) & 63;
#pragma unroll
            for (int jp = 0; jp < 2; jp++) {
                const int colb = ntile * 128 + warp_n * 32 + jp * 16 + (lane & 3) * 2;
                const int hh = colb >> 6;
                const int ks2 = (colb & 63) >> 4;
                uint32_t hw[4], lw[4];
#pragma unroll
                for (int half = 0; half < 2; half++) {
#pragma unroll
                    for (int jj = 0; jj < 2; jj++) {
                        const int j = jp * 2 + jj;
                        const int c = ntile * 128 + warp_n * 32 + j * 8 + (lane & 3) * 2;
                        float v0 = acc[i][j][half * 2 + 0] + bias[c];
                        float v1 = acc[i][j][half * 2 + 1] + bias[c + 1];
                        split_pair(v0, v1, hw[jj + half * 2], lw[jj + half * 2]);
                    }
                }
                size_t widx =
                    ((((size_t)((bb * 16 + hh) * 64 + n16)) * 4 + ks2) * 32 + lane) * 4;
                *(uint4*)&fhi[widx] = make_uint4(hw[0], hw[1], hw[2], hw[3]);
                *(uint4*)&flo[widx] = make_uint4(lw[0], lw[1], lw[2], lw[3]);
            }
        }
        return;
    }

#pragma unroll
    for (int i = 0; i < 4; i++) {
        const int row0 = mtile * 128 + warp_m * 64 + i * 16 + (lane >> 2);
#pragma unroll
        for (int j = 0; j < 4; j++) {
            const int col0 = ntile * 128 + warp_n * 32 + j * 8 + (lane & 3) * 2;
            const float b0 = bias[col0], b1 = bias[col0 + 1];
#pragma unroll
            for (int half = 0; half < 2; half++) {
                const int row = row0 + half * 8;
                float v0 = acc[i][j][half * 2 + 0] + b0;
                float v1 = acc[i][j][half * 2 + 1] + b1;
                if (MODE == 0) {
                    v0 *= scale; v1 *= scale;
                    const int bb = row >> 10, ss = row & 1023;
                    const int hh = col0 >> 6, dk = col0 & 63;
                    float* dst = out + ((((size_t)(bb * 16 + hh)) << 10) + ss) * 64 + dk;
                    *(float2*)dst = make_float2(v0, v1);
                } else {
                    *(float2*)(out + (size_t)row * 1024 + col0) = make_float2(v0, v1);
                }
            }
        }
    }
}

// ---------------------------------------------------------------------------
// qrel[bhs][t] = sum_d qp[bhs][d] * rel_k[t][d]   (q already scaled)
// ---------------------------------------------------------------------------
__global__ __launch_bounds__(256) void k_qrel(const float* __restrict__ qp,
                                              const float* __restrict__ rel_k,
                                              float* __restrict__ qrel)
{
    __shared__ float rk[V_ * 65];
    __shared__ float qs[8 * DK_];
    const int tid = threadIdx.x;
    const long long r0 = (long long)blockIdx.x * 8;
    for (int i = tid; i < V_ * DK_; i += 256) {
        int t = i / DK_, d = i % DK_;
        rk[t * 65 + d] = rel_k[i];
    }
    for (int i = tid; i < 8 * DK_; i += 256) qs[i] = qp[r0 * DK_ + i];
    __syncthreads();
    const int wr = tid >> 5, lane = tid & 31;
    for (int t = lane; t < V_; t += 32) {
        float s = 0.f;
#pragma unroll
        for (int d = 0; d < DK_; d++) s += qs[wr * DK_ + d] * rk[t * 65 + d];
        qrel[(r0 + wr) * V_ + t] = s;
    }
}

// fold helper: -log(adj) with adj in {1,2} fast paths
__device__ __forceinline__ float adj_fold(float av) {
    if (av == 1.0f) return 0.f;
    if (av == 2.0f) return 0.69314718055994530942f;
    return __logf(av);
}

// ---------------------------------------------------------------------------
// Pass A: QK mma + fold + p = exp(s) store (no max subtraction — scores are
// bounded) + plain row sum. stats = 1/sum.
// grid (8 qtiles, 128 bh), 256 thr; warp = 16 q rows x all 1024 k.
// ---------------------------------------------------------------------------
__global__ __launch_bounds__(256) void k_qk_stats(
    const float* __restrict__ qp,
    const uint4* __restrict__ Khi, const uint4* __restrict__ Klo,
    const float* __restrict__ qrel, const void* __restrict__ mask,
    const float* __restrict__ adj, float* __restrict__ pu,
    float* __restrict__ stats)
{
    const int tid = threadIdx.x, lane = tid & 31, wid = tid >> 5;
    const int qtile = blockIdx.x, bh = blockIdx.y;
    const int row0 = qtile * 128 + wid * 16 + (lane >> 2);
    const int row1 = row0 + 8;
    const size_t qbase = ((size_t)bh << 10);

    // Q fragments directly from qp (split on the fly, reused for all k)
    uint32_t qh[4][4], ql[4][4];
#pragma unroll
    for (int ks = 0; ks < 4; ks++) {
        const int c0 = ks * 16 + (lane & 3) * 2;
        float2 x0 = *(const float2*)(qp + (qbase + row0) * 64 + c0);
        float2 x1 = *(const float2*)(qp + (qbase + row1) * 64 + c0);
        float2 x2 = *(const float2*)(qp + (qbase + row0) * 64 + c0 + 8);
        float2 x3 = *(const float2*)(qp + (qbase + row1) * 64 + c0 + 8);
        split_pair(x0.x, x0.y, qh[ks][0], ql[ks][0]);
        split_pair(x1.x, x1.y, qh[ks][1], ql[ks][1]);
        split_pair(x2.x, x2.y, qh[ks][2], ql[ks][2]);
        split_pair(x3.x, x3.y, qh[ks][3], ql[ks][3]);
    }

    const int mode = g_mask_mode;
    const int bb = bh >> 4;
    const float* qr0 = qrel + (qbase + row0) * V_;
    const float* qr1 = qrel + (qbase + row1) * V_;
    const float qlo0 = qr0[0], qhi0 = qr0[64];
    const float qlo1 = qr1[0], qhi1 = qr1[64];
    const size_t arow0 = (qbase + row0) << 10;
    const size_t arow1 = (qbase + row1) << 10;
    const size_t mrow0 = (((size_t)bb << 10) + row0) << 10;
    const size_t mrow1 = (((size_t)bb << 10) + row1) << 10;
    const size_t kb = (size_t)bh * 8192;   // uint4 per head K image

    float s0 = 0.f, s1 = 0.f;

    for (int kt = 0; kt < 16; kt++) {      // 64-col tiles
        float acc[8][4];
#pragma unroll
        for (int p = 0; p < 8; p++)
#pragma unroll
            for (int c = 0; c < 4; c++) acc[p][c] = 0.f;

#pragma unroll
        for (int ks = 0; ks < 4; ks++) {
#pragma unroll
            for (int b = 0; b < 4; b++) {
                const int n16 = kt * 4 + b;
                const uint4 Bh = Khi[kb + (size_t)(n16 * 4 + ks) * 32 + lane];
                const uint4 Bl = Klo[kb + (size_t)(n16 * 4 + ks) * 32 + lane];
                mma_bf16(acc[b*2],   qh[ks][0], qh[ks][1], qh[ks][2], qh[ks][3], Bh.x, Bh.y);
                mma_bf16(acc[b*2],   ql[ks][0], ql[ks][1], ql[ks][2], ql[ks][3], Bh.x, Bh.y);
                mma_bf16(acc[b*2],   qh[ks][0], qh[ks][1], qh[ks][2], qh[ks][3], Bl.x, Bl.y);
                mma_bf16(acc[b*2+1], qh[ks][0], qh[ks][1], qh[ks][2], qh[ks][3], Bh.z, Bh.w);
                mma_bf16(acc[b*2+1], ql[ks][0], ql[ks][1], ql[ks][2], ql[ks][3], Bh.z, Bh.w);
                mma_bf16(acc[b*2+1], qh[ks][0], qh[ks][1], qh[ks][2], qh[ks][3], Bl.z, Bl.w);
            }
        }

        // tile-level relative-position classification (band is |k-q|<32)
        const int tlo = kt * 64;
        const bool pre0a = (tlo + 63 <= row0 - 32);
        const bool suf0a = (tlo >= row0 + 32);
        const bool pre1a = (tlo + 63 <= row1 - 32);
        const bool suf1a = (tlo >= row1 + 32);

#pragma unroll
        for (int p = 0; p < 8; p++) {
            const int col = tlo + p * 8 + (lane & 3) * 2;
            // row0 pair
            {
                float r0x, r0y;
                if (pre0a)      { r0x = qlo0; r0y = qlo0; }
                else if (suf0a) { r0x = qhi0; r0y = qhi0; }
                else {
                    int d0 = col - row0;     d0 = d0 < -32 ? -32 : (d0 > 32 ? 32 : d0);
                    int d1 = col + 1 - row0; d1 = d1 < -32 ? -32 : (d1 > 32 ? 32 : d1);
                    r0x = qr0[d0 + 32]; r0y = qr0[d1 + 32];
                }
                float v0 = acc[p][0] + r0x;
                float v1 = acc[p][1] + r0y;
                float2 av = *(const float2*)(adj + arow0 + col);
                bool ma, mb;
                mask2_at(mask, mode, mrow0 + col, ma, mb);
                if (ma || av.x == 0.0f) v0 = -1e30f; else v0 -= adj_fold(av.x);
                if (mb || av.y == 0.0f) v1 = -1e30f; else v1 -= adj_fold(av.y);
                float p0 = __expf(v0), p1 = __expf(v1);
                *(float2*)(pu + arow0 + col) = make_float2(p0, p1);
                s0 += p0 + p1;
            }
            // row1 pair
            {
                float r1x, r1y;
                if (pre1a)      { r1x = qlo1; r1y = qlo1; }
                else if (suf1a) { r1x = qhi1; r1y = qhi1; }
                else {
                    int d0 = col - row1;     d0 = d0 < -32 ? -32 : (d0 > 32 ? 32 : d0);
                    int d1 = col + 1 - row1; d1 = d1 < -32 ? -32 : (d1 > 32 ? 32 : d1);
                    r1x = qr1[d0 + 32]; r1y = qr1[d1 + 32];
                }
                float v0 = acc[p][2] + r1x;
                float v1 = acc[p][3] + r1y;
                float2 av = *(const float2*)(adj + arow1 + col);
                bool ma, mb;
                mask2_at(mask, mode, mrow1 + col, ma, mb);
                if (ma || av.x == 0.0f) v0 = -1e30f; else v0 -= adj_fold(av.x);
                if (mb || av.y == 0.0f) v1 = -1e30f; else v1 -= adj_fold(av.y);
                float p0 = __expf(v0), p1 = __expf(v1);
                *(float2*)(pu + arow1 + col) = make_float2(p0, p1);
                s1 += p0 + p1;
            }
        }
    }

    // combine sums across the 4 lanes sharing each row
#pragma unroll
    for (int o = 1; o <= 2; o <<= 1) {
        s0 += __shfl_xor_sync(0xffffffffu, s0, o);
        s1 += __shfl_xor_sync(0xffffffffu, s1, o);
    }
    if ((lane & 3) == 0) {
        stats[qbase + row0] = s0 > 0.f ? 1.f / s0 : 0.f;
        stats[qbase + row1] = s1 > 0.f ? 1.f / s1 : 0.f;
    }
}

// ---------------------------------------------------------------------------
// Pass B: read p, attn = p*inv, write attn to d_out, rel-value buckets, and
// AV via mma with attn repacked in-register as A fragments.
// grid (8 qtiles, 128 bh), 256 thr; warp = 16 q rows.
// ---------------------------------------------------------------------------
__global__ __launch_bounds__(256) void k_av_fused(
    const float* __restrict__ pu,
    const uint4* __restrict__ Vhi, const uint4* __restrict__ Vlo,
    const float* __restrict__ stats, float* __restrict__ wbuf,
    float* __restrict__ attn_out, float* __restrict__ ctx)
{
    const int tid = threadIdx.x, lane = tid & 31, wid = tid >> 5;
    const int qtile = blockIdx.x, bh = blockIdx.y;
    const int row0 = qtile * 128 + wid * 16 + (lane >> 2);
    const int row1 = row0 + 8;
    const size_t grow0 = ((size_t)bh << 10) + row0;

    const float inv0 = stats[grow0];
    const float inv1 = stats[grow0 + 8];

    // zero this warp's 16 wbuf rows
    const size_t wrbase = ((size_t)bh << 10) + qtile * 128 + wid * 16;
    for (int i = lane; i < 16 * V_; i += 32) wbuf[wrbase * V_ + i] = 0.f;
    __syncwarp();

    float cacc[4][2][4];
#pragma unroll
    for (int nb = 0; nb < 4; nb++)
#pragma unroll
        for (int e = 0; e < 2; e++)
#pragma unroll
            for (int c = 0; c < 4; c++) cacc[nb][e][c] = 0.f;

    float pre0 = 0.f, suf0 = 0.f, pre1 = 0.f, suf1 = 0.f;
    const float* s0p = pu + (grow0 << 10);
    const float* s1p = s0p + (size_t)8 * 1024;
    float* a0p = attn_out ? attn_out + (grow0 << 10) : nullptr;
    float* wr0 = wbuf + grow0 * V_;
    float* wr1 = wr0 + (size_t)8 * V_;
    const size_t vb = (size_t)bh * 8192;

#pragma unroll 2
    for (int kstep = 0; kstep < 64; kstep++) {
        const int col = kstep * 16 + (lane & 3) * 2;
        float2 v00 = *(const float2*)(s0p + col);
        float2 v01 = *(const float2*)(s0p + col + 8);
        float2 v10 = *(const float2*)(s1p + col);
        float2 v11 = *(const float2*)(s1p + col + 8);
        v00.x *= inv0; v00.y *= inv0;
        v01.x *= inv0; v01.y *= inv0;
        v10.x *= inv1; v10.y *= inv1;
        v11.x *= inv1; v11.y *= inv1;
        if (a0p) {
            *(float2*)(a0p + col)              = v00;
            *(float2*)(a0p + col + 8)          = v01;
            *(float2*)(a0p + 8 * 1024 + col)     = v10;
            *(float2*)(a0p + 8 * 1024 + col + 8) = v11;
        }
        // rel-value buckets, tile-classified (tile = 16 cols)
        {
            const int tlo = kstep * 16;
            const float sum0 = v00.x + v00.y + v01.x + v01.y;
            const float sum1 = v10.x + v10.y + v11.x + v11.y;
            if (tlo + 15 <= row0 - 32)      pre0 += sum0;
            else if (tlo >= row0 + 32)      suf0 += sum0;
            else {
                float pv[4] = {v00.x, v00.y, v01.x, v01.y};
                int   kc[4] = {col, col + 1, col + 8, col + 9};
#pragma unroll
                for (int e = 0; e < 4; e++) {
                    int d = kc[e] - row0;
                    if (d <= -32)      pre0 += pv[e];
                    else if (d >= 32)  suf0 += pv[e];
                    else               wr0[d + 32] = pv[e];
                }
            }
            if (tlo + 15 <= row1 - 32)      pre1 += sum1;
            else if (tlo >= row1 + 32)      suf1 += sum1;
            else {
                float qv[4] = {v10.x, v10.y, v11.x, v11.y};
                int   kc[4] = {col, col + 1, col + 8, col + 9};
#pragma unroll
                for (int e = 0; e < 4; e++) {
                    int d = kc[e] - row1;
                    if (d <= -32)      pre1 += qv[e];
                    else if (d >= 32)  suf1 += qv[e];
                    else               wr1[d + 32] = qv[e];
                }
            }
        }
        // repack attn as A fragments (QK acc layout == AV A-frag layout)
        uint32_t ah0, ah1, ah2, ah3, al0, al1, al2, al3;
        split_pair(v00.x, v00.y, ah0, al0);
        split_pair(v10.x, v10.y, ah1, al1);
        split_pair(v01.x, v01.y, ah2, al2);
        split_pair(v11.x, v11.y, ah3, al3);
#pragma unroll
        for (int nb = 0; nb < 4; nb++) {
            const uint4 Bh = Vhi[vb + (size_t)(nb * 64 + kstep) * 32 + lane];
            const uint4 Bl = Vlo[vb + (size_t)(nb * 64 + kstep) * 32 + lane];
            mma_bf16(cacc[nb][0], ah0, ah1, ah2, ah3, Bh.x, Bh.y);
            mma_bf16(cacc[nb][0], al0, al1, al2, al3, Bh.x, Bh.y);
            mma_bf16(cacc[nb][0], ah0, ah1, ah2, ah3, Bl.x, Bl.y);
            mma_bf16(cacc[nb][1], ah0, ah1, ah2, ah3, Bh.z, Bh.w);
            mma_bf16(cacc[nb][1], al0, al1, al2, al3, Bh.z, Bh.w);
            mma_bf16(cacc[nb][1], ah0, ah1, ah2, ah3, Bl.z, Bl.w);
        }
    }

    // reduce pre/suf across the 4 lanes per row, write bucket endpoints
#pragma unroll
    for (int o = 1; o <= 2; o <<= 1) {
        pre0 += __shfl_xor_sync(0xffffffffu, pre0, o);
        suf0 += __shfl_xor_sync(0xffffffffu, suf0, o);
        pre1 += __shfl_xor_sync(0xffffffffu, pre1, o);
        suf1 += __shfl_xor_sync(0xffffffffu, suf1, o);
    }
    if ((lane & 3) == 0) {
        wr0[0] = pre0; wr0[64] = suf0;
        wr1[0] = pre1; wr1[64] = suf1;
    }

    // ctx write [b][s][h*64+d]
    const int bb = bh >> 4, hh = bh & 15;
#pragma unroll
    for (int nb = 0; nb < 4; nb++)
#pragma unroll
        for (int e = 0; e < 2; e++) {
            const int d = nb * 16 + e * 8 + (lane & 3) * 2;
#pragma unroll
            for (int half = 0; half < 2; half++) {
                const int q = row0 + half * 8;
                float2 v = make_float2(cacc[nb][e][half * 2 + 0],
                                       cacc[nb][e][half * 2 + 1]);
                *(float2*)(ctx + (((size_t)bb << 10) + q) * 1024 + hh * 64 + d) = v;
            }
        }
}

// ---------------------------------------------------------------------------
// ctx += w @ rel_v   (65x64 per row)
// ---------------------------------------------------------------------------
__global__ __launch_bounds__(256) void k_relctx(const float* __restrict__ wbuf,
                                                const float* __restrict__ rel_v,
                                                float* __restrict__ ctx)
{
    __shared__ float rv[V_ * 64];
    __shared__ float ws[4][V_];
    const int tid = threadIdx.x;
    const long long r0 = (long long)blockIdx.x * 4;
    for (int i = tid; i < V_ * 64; i += 256) rv[i] = rel_v[i];
    for (int i = tid; i < 4 * V_; i += 256)
        ws[i / V_][i % V_] = wbuf[(r0 + i / V_) * V_ + i % V_];
    __syncthreads();
    const int rr = tid >> 6;
    const int d = tid & 63;
    float acc = 0.f;
#pragma unroll
    for (int t = 0; t < V_; t++) acc += ws[rr][t] * rv[t * 64 + d];
    long long r = r0 + rr;
    int bh = (int)(r >> 10), s = (int)(r & 1023);
    int bb = bh >> 4, hh = bh & 15;
    ctx[((size_t)(bb * S_ + s)) * D_ + hh * 64 + d] += acc;
}

// ---------------------------------------------------------------------------
// Launch
// ---------------------------------------------------------------------------
extern "C" void kernel_launch(void* const* d_in, const int* in_sizes, int n_in,
                              void* d_out, int out_size)
{
    const float* key   = (const float*)d_in[0];
    const float* value = (const float*)d_in[1];
    const float* query = (const float*)d_in[2];
    const void*  mask  = d_in[3];
    const float* adj   = (const float*)d_in[4];
    const float* Wq = (const float*)d_in[5];
    const float* bq = (const float*)d_in[6];
    const float* Wk = (const float*)d_in[7];
    const float* bk = (const float*)d_in[8];
    const float* Wv = (const float*)d_in[9];
    const float* bv = (const float*)d_in[10];
    const float* Wo = (const float*)d_in[11];
    const float* bo = (const float*)d_in[12];
    const float* rel_k = (const float*)d_in[13];
    const float* rel_v = (const float*)d_in[14];
    float* outF = (float*)d_out;

    float *qp, *vp, *qrel, *wb, *sc, *ctx, *stats;
    uint32_t *ahi, *alo, *whi, *wlo, *khi, *klo, *vhi, *vlo;
    cudaGetSymbolAddress((void**)&qp,    g_qp);
    cudaGetSymbolAddress((void**)&vp,    g_vp);
    cudaGetSymbolAddress((void**)&qrel,  g_qrel);
    cudaGetSymbolAddress((void**)&wb,    g_w);
    cudaGetSymbolAddress((void**)&sc,    g_scores);
    cudaGetSymbolAddress((void**)&ctx,   g_ctx);
    cudaGetSymbolAddress((void**)&stats, g_stats);
    cudaGetSymbolAddress((void**)&ahi,   g_Ahi);
    cudaGetSymbolAddress((void**)&alo,   g_Alo);
    cudaGetSymbolAddress((void**)&whi,   g_Whi);
    cudaGetSymbolAddress((void**)&wlo,   g_Wlo);
    cudaGetSymbolAddress((void**)&khi,   g_Khi);
    cudaGetSymbolAddress((void**)&klo,   g_Klo);
    cudaGetSymbolAddress((void**)&vhi,   g_Vhi);
    cudaGetSymbolAddress((void**)&vlo,   g_Vlo);

    // mask dtype detection
    k_reset_flags<<<1, 1>>>();
    k_detect_mask<<<256, 256>>>((const unsigned*)mask, in_sizes[3] / 4);
    k_finalize_mask<<<1, 1>>>();

    const int APACK_BLOCKS = MROWS * D_ / 2 / 256;   // 16384
    const int WPACK_BLOCKS = D_ * D_ / 2 / 256;      // 2048
    const int HPACK_BLOCKS = HEADW / 256;            // 16384
    dim3 gg(8, 64);   // (ntiles, mtiles)

    // Q projection (pre-scaled by 1/8 incl. bias)
    k_pack_w<<<WPACK_BLOCKS, 256>>>(Wq, whi, wlo);
    k_pack_a<<<APACK_BLOCKS, 256>>>(query, ahi, alo);
    k_mma_gemm<0><<<gg, 256>>>((const uint4*)ahi, (const uint4*)alo,
                               (const uint4*)whi, (const uint4*)wlo, bq, 0.125f, qp,
                               nullptr, nullptr);

    // K projection — emits K B-fragment images directly
    k_pack_w<<<WPACK_BLOCKS, 256>>>(Wk, whi, wlo);
    k_pack_a<<<APACK_BLOCKS, 256>>>(key, ahi, alo);
    k_mma_gemm<2><<<gg, 256>>>((const uint4*)ahi, (const uint4*)alo,
                               (const uint4*)whi, (const uint4*)wlo, bk, 1.0f, nullptr,
                               khi, klo);

    // V projection
    k_pack_w<<<WPACK_BLOCKS, 256>>>(Wv, whi, wlo);
    k_pack_a<<<APACK_BLOCKS, 256>>>(value, ahi, alo);
    k_mma_gemm<0><<<gg, 256>>>((const uint4*)ahi, (const uint4*)alo,
                               (const uint4*)whi, (const uint4*)wlo, bv, 1.0f, vp,
                               nullptr, nullptr);

    // V B-fragment pack
    k_pack_vb<<<HPACK_BLOCKS, 256>>>(vp, vhi, vlo);

    // relative-key projection (rank-65 trick)
    k_qrel<<<NROW / 8, 256>>>(qp, rel_k, qrel);

    // Pass A: p = exp(folded scores) + row sums (no max — scores bounded)
    dim3 ag(8, BH_);
    k_qk_stats<<<ag, 256>>>(qp, (const uint4*)khi, (const uint4*)klo,
                            qrel, mask, adj, sc, stats);

    // Pass B: normalize + attn out + buckets + AV
    bool hasAttn = (size_t)out_size >= (size_t)FINAL_ELEMS + SCORES_ELEMS;
    float* attnOut = hasAttn ? outF + FINAL_ELEMS : nullptr;
    k_av_fused<<<ag, 256>>>(sc, (const uint4*)vhi, (const uint4*)vlo,
                            stats, wb, attnOut, ctx);

    k_relctx<<<NROW / 4, 256>>>(wb, rel_v, ctx);

    // output projection (row-major epilogue)
    k_pack_w<<<WPACK_BLOCKS, 256>>>(Wo, whi, wlo);
    k_pack_a<<<APACK_BLOCKS, 256>>>(ctx, ahi, alo);
    k_mma_gemm<1><<<gg, 256>>>((const uint4*)ahi, (const uint4*)alo,
                               (const uint4*)whi, (const uint4*)wlo, bo, 1.0f, outF,
                               nullptr, nullptr);
}

// round 14
// speedup vs baseline: 1.2669x; 1.0241x over previous
#include <cuda_runtime.h>
#include <cuda_bf16.h>
#include <cuda_fp16.h>
#include <cstdint>

// ---------------------------------------------------------------------------
// Problem constants
// ---------------------------------------------------------------------------
static constexpr int B_  = 8;
static constexpr int S_  = 1024;
static constexpr int D_  = 1024;
static constexpr int H_  = 16;
static constexpr int DK_ = 64;
static constexpr int V_  = 65;            // 2*MAXREL+1
static constexpr int BH_ = B_ * H_;       // 128
static constexpr int MROWS = B_ * S_;     // 8192
static constexpr int NROW  = BH_ * S_;    // 131072 (b,h,s) rows
static constexpr size_t SCORES_ELEMS = (size_t)BH_ * S_ * S_;  // 134217728
static constexpr int FINAL_ELEMS = MROWS * D_;                 // 8388608

// ---------------------------------------------------------------------------
// Device scratch (static — no allocation allowed)
// ---------------------------------------------------------------------------
__device__ float g_qp[BH_ * S_ * DK_];     // Q projection, [bh][s][d], pre-scaled 1/8
__device__ float g_vp[BH_ * S_ * DK_];
__device__ float g_qrel[NROW * V_];        // q . rel_k[t]
__device__ float g_w[NROW * V_];           // relative-value buckets
__device__ __half g_scores[SCORES_ELEMS];  // unnormalized p = exp(folded score), fp16
__device__ float g_ctx[MROWS * D_];        // [b][s][h*64+d]
__device__ float g_stats[NROW];            // per-row 1/sum
__device__ unsigned g_flags;
__device__ int g_mask_mode;

// bf16 split-precision fragment images (mma.sync m16n8k16 register order)
__device__ uint32_t g_Ahi[MROWS * D_ / 2];   // 16MB
__device__ uint32_t g_Alo[MROWS * D_ / 2];   // 16MB
__device__ uint32_t g_Whi[D_ * D_ / 2];      // 2MB
__device__ uint32_t g_Wlo[D_ * D_ / 2];      // 2MB

// per-head fragment images for K (QK B-operand) and V (AV B-operand)
static constexpr int HEADW = BH_ * S_ * DK_ / 2;   // 4.19M words each
__device__ uint32_t g_Khi[HEADW];
__device__ uint32_t g_Klo[HEADW];
__device__ uint32_t g_Vhi[HEADW];
__device__ uint32_t g_Vlo[HEADW];

// ---------------------------------------------------------------------------
// bf16 split helpers
// ---------------------------------------------------------------------------
__device__ __forceinline__ void split_pair(float x0, float x1,
                                           uint32_t& h, uint32_t& l) {
    __nv_bfloat16 h0 = __float2bfloat16(x0);
    __nv_bfloat16 h1 = __float2bfloat16(x1);
    __nv_bfloat16 l0 = __float2bfloat16(x0 - __bfloat162float(h0));
    __nv_bfloat16 l1 = __float2bfloat16(x1 - __bfloat162float(h1));
    h = (uint32_t)__bfloat16_as_ushort(h0) | ((uint32_t)__bfloat16_as_ushort(h1) << 16);
    l = (uint32_t)__bfloat16_as_ushort(l0) | ((uint32_t)__bfloat16_as_ushort(l1) << 16);
}

// mma.sync m16n8k16 bf16: C += A*B (A row-major 16x16, B col-major 16x8)
__device__ __forceinline__ void mma_bf16(float* c,
                                         uint32_t a0, uint32_t a1, uint32_t a2, uint32_t a3,
                                         uint32_t b0, uint32_t b1) {
    asm volatile(
        "mma.sync.aligned.m16n8k16.row.col.f32.bf16.bf16.f32 "
        "{%0,%1,%2,%3}, {%4,%5,%6,%7}, {%8,%9}, {%0,%1,%2,%3};"
        : "+f"(c[0]), "+f"(c[1]), "+f"(c[2]), "+f"(c[3])
        : "r"(a0), "r"(a1), "r"(a2), "r"(a3), "r"(b0), "r"(b1));
}

// ---------------------------------------------------------------------------
// Mask dtype detection (bool serialization is ambiguous: f32/u8/i32/bf16)
// ---------------------------------------------------------------------------
__global__ void k_reset_flags() { g_flags = 0u; }

__global__ void k_detect_mask(const unsigned* __restrict__ w, int n) {
    unsigned f = 0;
    for (int i = blockIdx.x * blockDim.x + threadIdx.x; i < n;
         i += gridDim.x * blockDim.x) {
        unsigned x = w[i];
        if (x == 0u) continue;
        if (x == 0x3F800000u) { f |= 1u; continue; }
        if ((x & ~0x01010101u) == 0u) { f |= (x == 1u) ? 16u : 2u; continue; }
        unsigned lo = x & 0xFFFFu, hi = x >> 16;
        if ((lo == 0u || lo == 0x3F80u) && (hi == 0u || hi == 0x3F80u)) f |= 4u;
        else f |= 8u;
    }
    if (f) atomicOr(&g_flags, f);
}

__global__ void k_finalize_mask() {
    unsigned fl = g_flags;
    int m;
    if      (fl & 4u) m = 3;
    else if (fl & 1u) m = 0;
    else if (fl & 2u) m = 1;
    else              m = 2;
    g_mask_mode = m;
}

// paired mask test: elements idx, idx+1 with a single load
__device__ __forceinline__ void mask2_at(const void* m, int mode, size_t idx,
                                         bool& a, bool& b) {
    if (mode == 1) {
        unsigned short w = *(const unsigned short*)((const unsigned char*)m + idx);
        a = (w & 0xFFu) != 0; b = (w >> 8) != 0;
    } else if (mode == 0) {
        float2 v = *(const float2*)((const float*)m + idx);
        a = v.x != 0.0f; b = v.y != 0.0f;
    } else if (mode == 3) {
        unsigned w = *(const unsigned*)((const unsigned short*)m + idx);
        a = (w & 0xFFFFu) != 0; b = (w >> 16) != 0;
    } else {
        int2 v = *(const int2*)((const int*)m + idx);
        a = v.x != 0; b = v.y != 0;
    }
}

// ---------------------------------------------------------------------------
// Pack A[8192,1024] fp32 -> hi/lo fragment images (projection GEMM operand).
// ---------------------------------------------------------------------------
__global__ __launch_bounds__(256) void k_pack_a(
    const float* __restrict__ src,
    uint32_t* __restrict__ hi, uint32_t* __restrict__ lo)
{
    int idx = blockIdx.x * 256 + threadIdx.x;
    int r    = idx & 3;
    int lane = (idx >> 2) & 31;
    int ks   = (idx >> 7) & 63;
    int mblk = idx >> 13;
    int row = mblk * 16 + (lane >> 2) + (r & 1) * 8;
    int col = ks * 16 + (lane & 3) * 2 + (r >> 1) * 8;
    float2 x = *(const float2*)(src + (size_t)row * 1024 + col);
    uint32_t h, l;
    split_pair(x.x, x.y, h, l);
    hi[idx] = h; lo[idx] = l;
}

// ---------------------------------------------------------------------------
// Pack W[1024k,1024n] fp32 -> hi/lo B fragment images (col-major operand).
// ---------------------------------------------------------------------------
__global__ __launch_bounds__(256) void k_pack_w(
    const float* __restrict__ W,
    uint32_t* __restrict__ hi, uint32_t* __restrict__ lo)
{
    int idx = blockIdx.x * 256 + threadIdx.x;
    int r    = idx & 3;
    int lane = (idx >> 2) & 31;
    int ks   = (idx >> 7) & 63;
    int n16  = idx >> 13;
    int n = n16 * 16 + (r >> 1) * 8 + (lane >> 2);
    int k = ks * 16 + (lane & 3) * 2 + (r & 1) * 8;
    float x0 = W[(size_t)k * 1024 + n];
    float x1 = W[(size_t)(k + 1) * 1024 + n];
    uint32_t h, l;
    split_pair(x0, x1, h, l);
    hi[idx] = h; lo[idx] = l;
}

// V as B-operand: vp[bh][s][64], B[k=s][n=d] = vp[k][n] -> [bh][n16=4][ks64][lane][4]
__global__ __launch_bounds__(256) void k_pack_vb(
    const float* __restrict__ vp,
    uint32_t* __restrict__ hi, uint32_t* __restrict__ lo)
{
    int idx = blockIdx.x * 256 + threadIdx.x;
    int r    = idx & 3;
    int lane = (idx >> 2) & 31;
    int ks   = (idx >> 7) & 63;
    int n16  = (idx >> 13) & 3;
    int bh   = idx >> 15;
    int n = n16 * 16 + (r >> 1) * 8 + (lane >> 2);
    int k = ks * 16 + (lane & 3) * 2 + (r & 1) * 8;
    float x0 = vp[(((size_t)bh << 10) + k) * 64 + n];
    float x1 = vp[(((size_t)bh << 10) + k + 1) * 64 + n];
    uint32_t h, l;
    split_pair(x0, x1, h, l);
    hi[idx] = h; lo[idx] = l;
}

// ---------------------------------------------------------------------------
// Tensor-core split-bf16 GEMM: C[8192,1024] = A @ W (+bias, epilogue layout)
// MODE 0: head layout [b,h,s,64] with (acc+bias)*scale
// MODE 1: row-major [M,N] + bias
// MODE 2: emit K B-fragment images (khi/klo) directly, coalesced uint4 stores
// ---------------------------------------------------------------------------
template <int MODE>
__global__ __launch_bounds__(256) void k_mma_gemm(
    const uint4* __restrict__ Ahi, const uint4* __restrict__ Alo,
    const uint4* __restrict__ Bhi, const uint4* __restrict__ Blo,
    const float* __restrict__ bias, float scale, float* __restrict__ out,
    uint32_t* __restrict__ fhi, uint32_t* __restrict__ flo)
{
    const int tid = threadIdx.x, lane = tid & 31, wid = tid >> 5;
    const int warp_m = wid & 1, warp_n = wid >> 1;
    const int ntile = blockIdx.x, mtile = blockIdx.y;
    const int mb0 = mtile * 8 + warp_m * 4;
    const int nb0 = ntile * 8 + warp_n * 2;

    float acc[4][4][4];
#pragma unroll
    for (int i = 0; i < 4; i++)
#pragma unroll
        for (int j = 0; j < 4; j++)
#pragma unroll
            for (int c = 0; c < 4; c++) acc[i][j][c] = 0.f;

    uint4 ah[2][4], al[2][4], bh[2][2], bl[2][2];

#pragma unroll
    for (int i = 0; i < 4; i++) {
        ah[0][i] = Ahi[((size_t)(mb0 + i) * 64 + 0) * 32 + lane];
        al[0][i] = Alo[((size_t)(mb0 + i) * 64 + 0) * 32 + lane];
    }
#pragma unroll
    for (int j = 0; j < 2; j++) {
        bh[0][j] = Bhi[((size_t)(nb0 + j) * 64 + 0) * 32 + lane];
        bl[0][j] = Blo[((size_t)(nb0 + j) * 64 + 0) * 32 + lane];
    }

#pragma unroll 2
    for (int ks = 0; ks < 64; ks++) {
        const int cb = ks & 1, nb = cb ^ 1;
        if (ks + 1 < 64) {
#pragma unroll
            for (int i = 0; i < 4; i++) {
                ah[nb][i] = Ahi[((size_t)(mb0 + i) * 64 + ks + 1) * 32 + lane];
                al[nb][i] = Alo[((size_t)(mb0 + i) * 64 + ks + 1) * 32 + lane];
            }
#pragma unroll
            for (int j = 0; j < 2; j++) {
                bh[nb][j] = Bhi[((size_t)(nb0 + j) * 64 + ks + 1) * 32 + lane];
                bl[nb][j] = Blo[((size_t)(nb0 + j) * 64 + ks + 1) * 32 + lane];
            }
        }
#pragma unroll
        for (int i = 0; i < 4; i++) {
            const uint4 A = ah[cb][i], L = al[cb][i];
#pragma unroll
            for (int j = 0; j < 2; j++) {
                const uint4 Bh = bh[cb][j], Bl = bl[cb][j];
                mma_bf16(acc[i][j * 2], A.x, A.y, A.z, A.w, Bh.x, Bh.y);
                mma_bf16(acc[i][j * 2], L.x, L.y, L.z, L.w, Bh.x, Bh.y);
                mma_bf16(acc[i][j * 2], A.x, A.y, A.z, A.w, Bl.x, Bl.y);
                mma_bf16(acc[i][j * 2 + 1], A.x, A.y, A.z, A.w, Bh.z, Bh.w);
                mma_bf16(acc[i][j * 2 + 1], L.x, L.y, L.z, L.w, Bh.z, Bh.w);
                mma_bf16(acc[i][j * 2 + 1], A.x, A.y, A.z, A.w, Bl.z, Bl.w);
            }
        }
    }

    if (MODE == 2) {
#pragma unroll
        for (int i = 0; i < 4; i++) {
            const int row = mtile * 128 + warp_m * 64 + i * 16 + (lane >> 2);
            const int bb = row >> 10;
            const int n16 = (row >> 4) & 63;
#pragma unroll
            for (int jp = 0; jp < 2; jp++) {
                const int colb = ntile * 128 + warp_n * 32 + jp * 16 + (lane & 3) * 2;
                const int hh = colb >> 6;
                const int ks2 = (colb & 63) >> 4;
                uint32_t hw[4], lw[4];
#pragma unroll
                for (int half = 0; half < 2; half++) {
#pragma unroll
                    for (int jj = 0; jj < 2; jj++) {
                        const int j = jp * 2 + jj;
                        const int c = ntile * 128 + warp_n * 32 + j * 8 + (lane & 3) * 2;
                        float v0 = acc[i][j][half * 2 + 0] + bias[c];
                        float v1 = acc[i][j][half * 2 + 1] + bias[c + 1];
                        split_pair(v0, v1, hw[jj + half * 2], lw[jj + half * 2]);
                    }
                }
                size_t widx =
                    ((((size_t)((bb * 16 + hh) * 64 + n16)) * 4 + ks2) * 32 + lane) * 4;
                *(uint4*)&fhi[widx] = make_uint4(hw[0], hw[1], hw[2], hw[3]);
                *(uint4*)&flo[widx] = make_uint4(lw[0], lw[1], lw[2], lw[3]);
            }
        }
        return;
    }

#pragma unroll
    for (int i = 0; i < 4; i++) {
        const int row0 = mtile * 128 + warp_m * 64 + i * 16 + (lane >> 2);
#pragma unroll
        for (int j = 0; j < 4; j++) {
            const int col0 = ntile * 128 + warp_n * 32 + j * 8 + (lane & 3) * 2;
            const float b0 = bias[col0], b1 = bias[col0 + 1];
#pragma unroll
            for (int half = 0; half < 2; half++) {
                const int row = row0 + half * 8;
                float v0 = acc[i][j][half * 2 + 0] + b0;
                float v1 = acc[i][j][half * 2 + 1] + b1;
                if (MODE == 0) {
                    v0 *= scale; v1 *= scale;
                    const int bb = row >> 10, ss = row & 1023;
                    const int hh = col0 >> 6, dk = col0 & 63;
                    float* dst = out + ((((size_t)(bb * 16 + hh)) << 10) + ss) * 64 + dk;
                    *(float2*)dst = make_float2(v0, v1);
                } else {
                    *(float2*)(out + (size_t)row * 1024 + col0) = make_float2(v0, v1);
                }
            }
        }
    }
}

// ---------------------------------------------------------------------------
// qrel[bhs][t] = sum_d qp[bhs][d] * rel_k[t][d]   (q already scaled)
// ---------------------------------------------------------------------------
__global__ __launch_bounds__(256) void k_qrel(const float* __restrict__ qp,
                                              const float* __restrict__ rel_k,
                                              float* __restrict__ qrel)
{
    __shared__ float rk[V_ * 65];
    __shared__ float qs[8 * DK_];
    const int tid = threadIdx.x;
    const long long r0 = (long long)blockIdx.x * 8;
    for (int i = tid; i < V_ * DK_; i += 256) {
        int t = i / DK_, d = i % DK_;
        rk[t * 65 + d] = rel_k[i];
    }
    for (int i = tid; i < 8 * DK_; i += 256) qs[i] = qp[r0 * DK_ + i];
    __syncthreads();
    const int wr = tid >> 5, lane = tid & 31;
    for (int t = lane; t < V_; t += 32) {
        float s = 0.f;
#pragma unroll
        for (int d = 0; d < DK_; d++) s += qs[wr * DK_ + d] * rk[t * 65 + d];
        qrel[(r0 + wr) * V_ + t] = s;
    }
}

// fold helper: -log(adj) with adj in {1,2} fast paths
__device__ __forceinline__ float adj_fold(float av) {
    if (av == 1.0f) return 0.f;
    if (av == 2.0f) return 0.69314718055994530942f;
    return __logf(av);
}

// ---------------------------------------------------------------------------
// Pass A: QK mma + fold + p = exp(s) stored fp16 (no max subtraction — scores
// bounded) + plain fp32 row sum. stats = 1/sum.
// grid (8 qtiles, 128 bh), 256 thr; warp = 16 q rows x all 1024 k.
// ---------------------------------------------------------------------------
__global__ __launch_bounds__(256) void k_qk_stats(
    const float* __restrict__ qp,
    const uint4* __restrict__ Khi, const uint4* __restrict__ Klo,
    const float* __restrict__ qrel, const void* __restrict__ mask,
    const float* __restrict__ adj, __half* __restrict__ pu,
    float* __restrict__ stats)
{
    const int tid = threadIdx.x, lane = tid & 31, wid = tid >> 5;
    const int qtile = blockIdx.x, bh = blockIdx.y;
    const int row0 = qtile * 128 + wid * 16 + (lane >> 2);
    const int row1 = row0 + 8;
    const size_t qbase = ((size_t)bh << 10);

    // Q fragments directly from qp (split on the fly, reused for all k)
    uint32_t qh[4][4], ql[4][4];
#pragma unroll
    for (int ks = 0; ks < 4; ks++) {
        const int c0 = ks * 16 + (lane & 3) * 2;
        float2 x0 = *(const float2*)(qp + (qbase + row0) * 64 + c0);
        float2 x1 = *(const float2*)(qp + (qbase + row1) * 64 + c0);
        float2 x2 = *(const float2*)(qp + (qbase + row0) * 64 + c0 + 8);
        float2 x3 = *(const float2*)(qp + (qbase + row1) * 64 + c0 + 8);
        split_pair(x0.x, x0.y, qh[ks][0], ql[ks][0]);
        split_pair(x1.x, x1.y, qh[ks][1], ql[ks][1]);
        split_pair(x2.x, x2.y, qh[ks][2], ql[ks][2]);
        split_pair(x3.x, x3.y, qh[ks][3], ql[ks][3]);
    }

    const int mode = g_mask_mode;
    const int bb = bh >> 4;
    const float* qr0 = qrel + (qbase + row0) * V_;
    const float* qr1 = qrel + (qbase + row1) * V_;
    const float qlo0 = qr0[0], qhi0 = qr0[64];
    const float qlo1 = qr1[0], qhi1 = qr1[64];
    const size_t arow0 = (qbase + row0) << 10;
    const size_t arow1 = (qbase + row1) << 10;
    const size_t mrow0 = (((size_t)bb << 10) + row0) << 10;
    const size_t mrow1 = (((size_t)bb << 10) + row1) << 10;
    const size_t kb = (size_t)bh * 8192;   // uint4 per head K image

    float s0 = 0.f, s1 = 0.f;

    for (int kt = 0; kt < 16; kt++) {      // 64-col tiles
        float acc[8][4];
#pragma unroll
        for (int p = 0; p < 8; p++)
#pragma unroll
            for (int c = 0; c < 4; c++) acc[p][c] = 0.f;

#pragma unroll
        for (int ks = 0; ks < 4; ks++) {
#pragma unroll
            for (int b = 0; b < 4; b++) {
                const int n16 = kt * 4 + b;
                const uint4 Bh = Khi[kb + (size_t)(n16 * 4 + ks) * 32 + lane];
                const uint4 Bl = Klo[kb + (size_t)(n16 * 4 + ks) * 32 + lane];
                mma_bf16(acc[b*2],   qh[ks][0], qh[ks][1], qh[ks][2], qh[ks][3], Bh.x, Bh.y);
                mma_bf16(acc[b*2],   ql[ks][0], ql[ks][1], ql[ks][2], ql[ks][3], Bh.x, Bh.y);
                mma_bf16(acc[b*2],   qh[ks][0], qh[ks][1], qh[ks][2], qh[ks][3], Bl.x, Bl.y);
                mma_bf16(acc[b*2+1], qh[ks][0], qh[ks][1], qh[ks][2], qh[ks][3], Bh.z, Bh.w);
                mma_bf16(acc[b*2+1], ql[ks][0], ql[ks][1], ql[ks][2], ql[ks][3], Bh.z, Bh.w);
                mma_bf16(acc[b*2+1], qh[ks][0], qh[ks][1], qh[ks][2], qh[ks][3], Bl.z, Bl.w);
            }
        }

        // tile-level relative-position classification (band is |k-q|<32)
        const int tlo = kt * 64;
        const bool pre0a = (tlo + 63 <= row0 - 32);
        const bool suf0a = (tlo >= row0 + 32);
        const bool pre1a = (tlo + 63 <= row1 - 32);
        const bool suf1a = (tlo >= row1 + 32);

#pragma unroll
        for (int p = 0; p < 8; p++) {
            const int col = tlo + p * 8 + (lane & 3) * 2;
            // row0 pair
            {
                float r0x, r0y;
                if (pre0a)      { r0x = qlo0; r0y = qlo0; }
                else if (suf0a) { r0x = qhi0; r0y = qhi0; }
                else {
                    int d0 = col - row0;     d0 = d0 < -32 ? -32 : (d0 > 32 ? 32 : d0);
                    int d1 = col + 1 - row0; d1 = d1 < -32 ? -32 : (d1 > 32 ? 32 : d1);
                    r0x = qr0[d0 + 32]; r0y = qr0[d1 + 32];
                }
                float v0 = acc[p][0] + r0x;
                float v1 = acc[p][1] + r0y;
                float2 av = *(const float2*)(adj + arow0 + col);
                bool ma, mb;
                mask2_at(mask, mode, mrow0 + col, ma, mb);
                if (ma || av.x == 0.0f) v0 = -1e30f; else v0 -= adj_fold(av.x);
                if (mb || av.y == 0.0f) v1 = -1e30f; else v1 -= adj_fold(av.y);
                float p0 = __expf(v0), p1 = __expf(v1);
                *(__half2*)(pu + arow0 + col) = __floats2half2_rn(p0, p1);
                s0 += p0 + p1;
            }
            // row1 pair
            {
                float r1x, r1y;
                if (pre1a)      { r1x = qlo1; r1y = qlo1; }
                else if (suf1a) { r1x = qhi1; r1y = qhi1; }
                else {
                    int d0 = col - row1;     d0 = d0 < -32 ? -32 : (d0 > 32 ? 32 : d0);
                    int d1 = col + 1 - row1; d1 = d1 < -32 ? -32 : (d1 > 32 ? 32 : d1);
                    r1x = qr1[d0 + 32]; r1y = qr1[d1 + 32];
                }
                float v0 = acc[p][2] + r1x;
                float v1 = acc[p][3] + r1y;
                float2 av = *(const float2*)(adj + arow1 + col);
                bool ma, mb;
                mask2_at(mask, mode, mrow1 + col, ma, mb);
                if (ma || av.x == 0.0f) v0 = -1e30f; else v0 -= adj_fold(av.x);
                if (mb || av.y == 0.0f) v1 = -1e30f; else v1 -= adj_fold(av.y);
                float p0 = __expf(v0), p1 = __expf(v1);
                *(__half2*)(pu + arow1 + col) = __floats2half2_rn(p0, p1);
                s1 += p0 + p1;
            }
        }
    }

    // combine sums across the 4 lanes sharing each row
#pragma unroll
    for (int o = 1; o <= 2; o <<= 1) {
        s0 += __shfl_xor_sync(0xffffffffu, s0, o);
        s1 += __shfl_xor_sync(0xffffffffu, s1, o);
    }
    if ((lane & 3) == 0) {
        stats[qbase + row0] = s0 > 0.f ? 1.f / s0 : 0.f;
        stats[qbase + row1] = s1 > 0.f ? 1.f / s1 : 0.f;
    }
}

// ---------------------------------------------------------------------------
// Pass B: read fp16 p, attn = p*inv, write attn (fp32) to d_out, rel-value
// buckets, and AV via mma with attn repacked in-register as A fragments.
// grid (8 qtiles, 128 bh), 256 thr; warp = 16 q rows.
// ---------------------------------------------------------------------------
__global__ __launch_bounds__(256) void k_av_fused(
    const __half* __restrict__ pu,
    const uint4* __restrict__ Vhi, const uint4* __restrict__ Vlo,
    const float* __restrict__ stats, float* __restrict__ wbuf,
    float* __restrict__ attn_out, float* __restrict__ ctx)
{
    const int tid = threadIdx.x, lane = tid & 31, wid = tid >> 5;
    const int qtile = blockIdx.x, bh = blockIdx.y;
    const int row0 = qtile * 128 + wid * 16 + (lane >> 2);
    const int row1 = row0 + 8;
    const size_t grow0 = ((size_t)bh << 10) + row0;

    const float inv0 = stats[grow0];
    const float inv1 = stats[grow0 + 8];

    // zero this warp's 16 wbuf rows
    const size_t wrbase = ((size_t)bh << 10) + qtile * 128 + wid * 16;
    for (int i = lane; i < 16 * V_; i += 32) wbuf[wrbase * V_ + i] = 0.f;
    __syncwarp();

    float cacc[4][2][4];
#pragma unroll
    for (int nb = 0; nb < 4; nb++)
#pragma unroll
        for (int e = 0; e < 2; e++)
#pragma unroll
            for (int c = 0; c < 4; c++) cacc[nb][e][c] = 0.f;

    float pre0 = 0.f, suf0 = 0.f, pre1 = 0.f, suf1 = 0.f;
    const __half* s0p = pu + (grow0 << 10);
    const __half* s1p = s0p + (size_t)8 * 1024;
    float* a0p = attn_out ? attn_out + (grow0 << 10) : nullptr;
    float* wr0 = wbuf + grow0 * V_;
    float* wr1 = wr0 + (size_t)8 * V_;
    const size_t vb = (size_t)bh * 8192;

#pragma unroll 2
    for (int kstep = 0; kstep < 64; kstep++) {
        const int col = kstep * 16 + (lane & 3) * 2;
        float2 v00 = __half22float2(*(const __half2*)(s0p + col));
        float2 v01 = __half22float2(*(const __half2*)(s0p + col + 8));
        float2 v10 = __half22float2(*(const __half2*)(s1p + col));
        float2 v11 = __half22float2(*(const __half2*)(s1p + col + 8));
        v00.x *= inv0; v00.y *= inv0;
        v01.x *= inv0; v01.y *= inv0;
        v10.x *= inv1; v10.y *= inv1;
        v11.x *= inv1; v11.y *= inv1;
        if (a0p) {
            *(float2*)(a0p + col)              = v00;
            *(float2*)(a0p + col + 8)          = v01;
            *(float2*)(a0p + 8 * 1024 + col)     = v10;
            *(float2*)(a0p + 8 * 1024 + col + 8) = v11;
        }
        // rel-value buckets, tile-classified (tile = 16 cols)
        {
            const int tlo = kstep * 16;
            const float sum0 = v00.x + v00.y + v01.x + v01.y;
            const float sum1 = v10.x + v10.y + v11.x + v11.y;
            if (tlo + 15 <= row0 - 32)      pre0 += sum0;
            else if (tlo >= row0 + 32)      suf0 += sum0;
            else {
                float pv[4] = {v00.x, v00.y, v01.x, v01.y};
                int   kc[4] = {col, col + 1, col + 8, col + 9};
#pragma unroll
                for (int e = 0; e < 4; e++) {
                    int d = kc[e] - row0;
                    if (d <= -32)      pre0 += pv[e];
                    else if (d >= 32)  suf0 += pv[e];
                    else               wr0[d + 32] = pv[e];
                }
            }
            if (tlo + 15 <= row1 - 32)      pre1 += sum1;
            else if (tlo >= row1 + 32)      suf1 += sum1;
            else {
                float qv[4] = {v10.x, v10.y, v11.x, v11.y};
                int   kc[4] = {col, col + 1, col + 8, col + 9};
#pragma unroll
                for (int e = 0; e < 4; e++) {
                    int d = kc[e] - row1;
                    if (d <= -32)      pre1 += qv[e];
                    else if (d >= 32)  suf1 += qv[e];
                    else               wr1[d + 32] = qv[e];
                }
            }
        }
        // repack attn as A fragments (QK acc layout == AV A-frag layout)
        uint32_t ah0, ah1, ah2, ah3, al0, al1, al2, al3;
        split_pair(v00.x, v00.y, ah0, al0);
        split_pair(v10.x, v10.y, ah1, al1);
        split_pair(v01.x, v01.y, ah2, al2);
        split_pair(v11.x, v11.y, ah3, al3);
#pragma unroll
        for (int nb = 0; nb < 4; nb++) {
            const uint4 Bh = Vhi[vb + (size_t)(nb * 64 + kstep) * 32 + lane];
            const uint4 Bl = Vlo[vb + (size_t)(nb * 64 + kstep) * 32 + lane];
            mma_bf16(cacc[nb][0], ah0, ah1, ah2, ah3, Bh.x, Bh.y);
            mma_bf16(cacc[nb][0], al0, al1, al2, al3, Bh.x, Bh.y);
            mma_bf16(cacc[nb][0], ah0, ah1, ah2, ah3, Bl.x, Bl.y);
            mma_bf16(cacc[nb][1], ah0, ah1, ah2, ah3, Bh.z, Bh.w);
            mma_bf16(cacc[nb][1], al0, al1, al2, al3, Bh.z, Bh.w);
            mma_bf16(cacc[nb][1], ah0, ah1, ah2, ah3, Bl.z, Bl.w);
        }
    }

    // reduce pre/suf across the 4 lanes per row, write bucket endpoints
#pragma unroll
    for (int o = 1; o <= 2; o <<= 1) {
        pre0 += __shfl_xor_sync(0xffffffffu, pre0, o);
        suf0 += __shfl_xor_sync(0xffffffffu, suf0, o);
        pre1 += __shfl_xor_sync(0xffffffffu, pre1, o);
        suf1 += __shfl_xor_sync(0xffffffffu, suf1, o);
    }
    if ((lane & 3) == 0) {
        wr0[0] = pre0; wr0[64] = suf0;
        wr1[0] = pre1; wr1[64] = suf1;
    }

    // ctx write [b][s][h*64+d]
    const int bb = bh >> 4, hh = bh & 15;
#pragma unroll
    for (int nb = 0; nb < 4; nb++)
#pragma unroll
        for (int e = 0; e < 2; e++) {
            const int d = nb * 16 + e * 8 + (lane & 3) * 2;
#pragma unroll
            for (int half = 0; half < 2; half++) {
                const int q = row0 + half * 8;
                float2 v = make_float2(cacc[nb][e][half * 2 + 0],
                                       cacc[nb][e][half * 2 + 1]);
                *(float2*)(ctx + (((size_t)bb << 10) + q) * 1024 + hh * 64 + d) = v;
            }
        }
}

// ---------------------------------------------------------------------------
// ctx += w @ rel_v   (65x64 per row)
// ---------------------------------------------------------------------------
__global__ __launch_bounds__(256) void k_relctx(const float* __restrict__ wbuf,
                                                const float* __restrict__ rel_v,
                                                float* __restrict__ ctx)
{
    __shared__ float rv[V_ * 64];
    __shared__ float ws[4][V_];
    const int tid = threadIdx.x;
    const long long r0 = (long long)blockIdx.x * 4;
    for (int i = tid; i < V_ * 64; i += 256) rv[i] = rel_v[i];
    for (int i = tid; i < 4 * V_; i += 256)
        ws[i / V_][i % V_] = wbuf[(r0 + i / V_) * V_ + i % V_];
    __syncthreads();
    const int rr = tid >> 6;
    const int d = tid & 63;
    float acc = 0.f;
#pragma unroll
    for (int t = 0; t < V_; t++) acc += ws[rr][t] * rv[t * 64 + d];
    long long r = r0 + rr;
    int bh = (int)(r >> 10), s = (int)(r & 1023);
    int bb = bh >> 4, hh = bh & 15;
    ctx[((size_t)(bb * S_ + s)) * D_ + hh * 64 + d] += acc;
}

// ---------------------------------------------------------------------------
// Launch
// ---------------------------------------------------------------------------
extern "C" void kernel_launch(void* const* d_in, const int* in_sizes, int n_in,
                              void* d_out, int out_size)
{
    const float* key   = (const float*)d_in[0];
    const float* value = (const float*)d_in[1];
    const float* query = (const float*)d_in[2];
    const void*  mask  = d_in[3];
    const float* adj   = (const float*)d_in[4];
    const float* Wq = (const float*)d_in[5];
    const float* bq = (const float*)d_in[6];
    const float* Wk = (const float*)d_in[7];
    const float* bk = (const float*)d_in[8];
    const float* Wv = (const float*)d_in[9];
    const float* bv = (const float*)d_in[10];
    const float* Wo = (const float*)d_in[11];
    const float* bo = (const float*)d_in[12];
    const float* rel_k = (const float*)d_in[13];
    const float* rel_v = (const float*)d_in[14];
    float* outF = (float*)d_out;

    float *qp, *vp, *qrel, *wb, *ctx, *stats;
    __half* sc;
    uint32_t *ahi, *alo, *whi, *wlo, *khi, *klo, *vhi, *vlo;
    cudaGetSymbolAddress((void**)&qp,    g_qp);
    cudaGetSymbolAddress((void**)&vp,    g_vp);
    cudaGetSymbolAddress((void**)&qrel,  g_qrel);
    cudaGetSymbolAddress((void**)&wb,    g_w);
    cudaGetSymbolAddress((void**)&sc,    g_scores);
    cudaGetSymbolAddress((void**)&ctx,   g_ctx);
    cudaGetSymbolAddress((void**)&stats, g_stats);
    cudaGetSymbolAddress((void**)&ahi,   g_Ahi);
    cudaGetSymbolAddress((void**)&alo,   g_Alo);
    cudaGetSymbolAddress((void**)&whi,   g_Whi);
    cudaGetSymbolAddress((void**)&wlo,   g_Wlo);
    cudaGetSymbolAddress((void**)&khi,   g_Khi);
    cudaGetSymbolAddress((void**)&klo,   g_Klo);
    cudaGetSymbolAddress((void**)&vhi,   g_Vhi);
    cudaGetSymbolAddress((void**)&vlo,   g_Vlo);

    // mask dtype detection
    k_reset_flags<<<1, 1>>>();
    k_detect_mask<<<256, 256>>>((const unsigned*)mask, in_sizes[3] / 4);
    k_finalize_mask<<<1, 1>>>();

    const int APACK_BLOCKS = MROWS * D_ / 2 / 256;   // 16384
    const int WPACK_BLOCKS = D_ * D_ / 2 / 256;      // 2048
    const int HPACK_BLOCKS = HEADW / 256;            // 16384
    dim3 gg(8, 64);   // (ntiles, mtiles)

    // Q projection (pre-scaled by 1/8 incl. bias)
    k_pack_w<<<WPACK_BLOCKS, 256>>>(Wq, whi, wlo);
    k_pack_a<<<APACK_BLOCKS, 256>>>(query, ahi, alo);
    k_mma_gemm<0><<<gg, 256>>>((const uint4*)ahi, (const uint4*)alo,
                               (const uint4*)whi, (const uint4*)wlo, bq, 0.125f, qp,
                               nullptr, nullptr);

    // K projection — emits K B-fragment images directly
    k_pack_w<<<WPACK_BLOCKS, 256>>>(Wk, whi, wlo);
    k_pack_a<<<APACK_BLOCKS, 256>>>(key, ahi, alo);
    k_mma_gemm<2><<<gg, 256>>>((const uint4*)ahi, (const uint4*)alo,
                               (const uint4*)whi, (const uint4*)wlo, bk, 1.0f, nullptr,
                               khi, klo);

    // V projection
    k_pack_w<<<WPACK_BLOCKS, 256>>>(Wv, whi, wlo);
    k_pack_a<<<APACK_BLOCKS, 256>>>(value, ahi, alo);
    k_mma_gemm<0><<<gg, 256>>>((const uint4*)ahi, (const uint4*)alo,
                               (const uint4*)whi, (const uint4*)wlo, bv, 1.0f, vp,
                               nullptr, nullptr);

    // V B-fragment pack
    k_pack_vb<<<HPACK_BLOCKS, 256>>>(vp, vhi, vlo);

    // relative-key projection (rank-65 trick)
    k_qrel<<<NROW / 8, 256>>>(qp, rel_k, qrel);

    // Pass A: p = exp(folded scores) fp16 + row sums (no max — scores bounded)
    dim3 ag(8, BH_);
    k_qk_stats<<<ag, 256>>>(qp, (const uint4*)khi, (const uint4*)klo,
                            qrel, mask, adj, sc, stats);

    // Pass B: normalize + attn out + buckets + AV
    bool hasAttn = (size_t)out_size >= (size_t)FINAL_ELEMS + SCORES_ELEMS;
    float* attnOut = hasAttn ? outF + FINAL_ELEMS : nullptr;
    k_av_fused<<<ag, 256>>>(sc, (const uint4*)vhi, (const uint4*)vlo,
                            stats, wb, attnOut, ctx);

    k_relctx<<<NROW / 4, 256>>>(wb, rel_v, ctx);

    // output projection (row-major epilogue)
    k_pack_w<<<WPACK_BLOCKS, 256>>>(Wo, whi, wlo);
    k_pack_a<<<APACK_BLOCKS, 256>>>(ctx, ahi, alo);
    k_mma_gemm<1><<<gg, 256>>>((const uint4*)ahi, (const uint4*)alo,
                               (const uint4*)whi, (const uint4*)wlo, bo, 1.0f, outF,
                               nullptr, nullptr);
}